// round 5
// baseline (speedup 1.0000x reference)
#include <cuda_runtime.h>
#include <cuda_bf16.h>

// ---------------------------------------------------------------------------
// NonLocalBlock: B=8, C=256, Ci=128, H=W=64, N=4096, M=1024
// ---------------------------------------------------------------------------

#define NB 8
#define CC 256
#define CI 128
#define NN 4096
#define MM 1024

typedef unsigned long long u64;

__device__ __forceinline__ u64 pack2(float lo, float hi) {
    u64 r; asm("mov.b64 %0, {%1, %2};" : "=l"(r) : "f"(lo), "f"(hi)); return r;
}
__device__ __forceinline__ void fma2(u64& d, u64 a, u64 b) {
    asm("fma.rn.f32x2 %0, %1, %2, %0;" : "+l"(d) : "l"(a), "l"(b));
}
__device__ __forceinline__ float2 unpack2(u64 v) {
    float2 f; asm("mov.b64 {%0, %1}, %2;" : "=f"(f.x), "=f"(f.y) : "l"(v)); return f;
}

// exp(x) for x <= 0 without MUFU: 2^(x*log2e) via exponent splice + deg-7 poly.
__device__ __forceinline__ float fast_exp(float x) {
    float y = x * 1.44269504088896340736f;
    y = fmaxf(y, -126.0f);
    float k = floorf(y);
    float f = y - k;
    const float c1 = 0.6931471805599453f, c2 = 0.2402265069591007f,
                c3 = 0.05550410866482158f, c4 = 0.009618129107628477f,
                c5 = 0.0013333558146428443f, c6 = 1.540353039338161e-4f,
                c7 = 1.52527338040598e-5f;
    float p = fmaf(c7, f, c6);
    p = fmaf(p, f, c5); p = fmaf(p, f, c4); p = fmaf(p, f, c3);
    p = fmaf(p, f, c2); p = fmaf(p, f, c1); p = fmaf(p, f, 1.0f);
    int ik = (int)k;
    float s = __int_as_float((ik + 127) << 23);
    return p * s;
}

// ----------------------------- scratch ------------------------------------
__device__ float g_theta[NB * CI * NN];
__device__ float g_phif [NB * CI * NN];
__device__ float g_gf   [NB * CI * NN];
__device__ float g_phip [NB * CI * MM];
__device__ float g_gp   [NB * CI * MM];
__device__ float g_y    [NB * CI * NN];
__device__ float g_z    [NB * CC * NN];
__device__ float g_psum [CC * 512];
__device__ float g_psumsq[CC * 512];
__device__ float g_bna[CC], g_bnb[CC];

// ---------------------------------------------------------------------------
// K1: three projection GEMMs, double-buffered k-tiles.
// ---------------------------------------------------------------------------
__global__ __launch_bounds__(256) void proj_kernel(
    const float* __restrict__ x,
    const float* __restrict__ tw, const float* __restrict__ tb,
    const float* __restrict__ pw, const float* __restrict__ pb,
    const float* __restrict__ gw, const float* __restrict__ gb)
{
    __shared__ float ws[2][16][64];
    __shared__ float xs[2][16][64];
    int b = blockIdx.z, ot = blockIdx.y, n0 = blockIdx.x * 64;
    const float *w, *bias; float* outb; int o0;
    if (ot < 2)      { w = tw; bias = tb; outb = g_theta; o0 = ot * 64; }
    else if (ot < 4) { w = pw; bias = pb; outb = g_phif;  o0 = (ot - 2) * 64; }
    else             { w = gw; bias = gb; outb = g_gf;    o0 = (ot - 4) * 64; }
    const float* xb = x + b * CC * NN;
    float* ob = outb + b * CI * NN;
    int tid = threadIdx.x, ty = tid >> 4, tx = tid & 15;
    int rr = tid >> 2, ss = tid & 3;
    u64 acc[4][2] = {};

    // preload tile 0
    {
        float4 wv = *(const float4*)&w[(o0 + rr) * CC + ss * 4];
        float4 xv = *(const float4*)&xb[ty * NN + n0 + tx * 4];
        ws[0][ss * 4 + 0][rr] = wv.x; ws[0][ss * 4 + 1][rr] = wv.y;
        ws[0][ss * 4 + 2][rr] = wv.z; ws[0][ss * 4 + 3][rr] = wv.w;
        *(float4*)&xs[0][ty][tx * 4] = xv;
    }
    int cur = 0;
    for (int kt = 0; kt < 16; kt++) {
        __syncthreads();
        float4 wv2, xv2;
        if (kt < 15) {
            wv2 = *(const float4*)&w[(o0 + rr) * CC + (kt + 1) * 16 + ss * 4];
            xv2 = *(const float4*)&xb[((kt + 1) * 16 + ty) * NN + n0 + tx * 4];
        }
#pragma unroll
        for (int k = 0; k < 16; k++) {
            float4 av = *(float4*)&ws[cur][k][ty * 4];
            float4 bv = *(float4*)&xs[cur][k][tx * 4];
            u64 b01 = pack2(bv.x, bv.y), b23 = pack2(bv.z, bv.w);
            u64 d;
            d = pack2(av.x, av.x); fma2(acc[0][0], d, b01); fma2(acc[0][1], d, b23);
            d = pack2(av.y, av.y); fma2(acc[1][0], d, b01); fma2(acc[1][1], d, b23);
            d = pack2(av.z, av.z); fma2(acc[2][0], d, b01); fma2(acc[2][1], d, b23);
            d = pack2(av.w, av.w); fma2(acc[3][0], d, b01); fma2(acc[3][1], d, b23);
        }
        if (kt < 15) {
            int nx = cur ^ 1;
            ws[nx][ss * 4 + 0][rr] = wv2.x; ws[nx][ss * 4 + 1][rr] = wv2.y;
            ws[nx][ss * 4 + 2][rr] = wv2.z; ws[nx][ss * 4 + 3][rr] = wv2.w;
            *(float4*)&xs[nx][ty][tx * 4] = xv2;
            cur = nx;
        }
    }
#pragma unroll
    for (int oi = 0; oi < 4; oi++) {
        int o = o0 + ty * 4 + oi;
        float bv = bias[o];
        float2 p0 = unpack2(acc[oi][0]), p1 = unpack2(acc[oi][1]);
        *(float4*)&ob[o * NN + n0 + tx * 4] =
            make_float4(p0.x + bv, p0.y + bv, p1.x + bv, p1.y + bv);
    }
}

// ---------------------------------------------------------------------------
// K1b: 2x2 max-pool for phi and g.
// ---------------------------------------------------------------------------
__global__ __launch_bounds__(256) void pool_kernel()
{
    int gid = blockIdx.x * 256 + threadIdx.x;
    const float* src; float* dst; int rid;
    if (gid < 524288) { src = g_phif; dst = g_phip; rid = gid; }
    else              { src = g_gf;   dst = g_gp;   rid = gid - 524288; }
    int wp = rid & 15, hp = (rid >> 4) & 31, bc = rid >> 9;
    const float* in = src + bc * 4096 + hp * 128 + wp * 4;
    float4 a = *(const float4*)in;
    float4 c = *(const float4*)(in + 64);
    float2 o;
    o.x = fmaxf(fmaxf(a.x, a.y), fmaxf(c.x, c.y));
    o.y = fmaxf(fmaxf(a.z, a.w), fmaxf(c.z, c.w));
    *(float2*)(dst + bc * 1024 + hp * 32 + wp * 2) = o;
}

// ---------------------------------------------------------------------------
// K2: fused flash-style attention. One CTA = (batch, 64 n-rows).
// Online softmax over m-chunks of 128. No full score tile.
// Thread (tn = tid&7, tm = tid>>3):
//   phase S: outputs S[m=tm*4+0..3][n=tn*8+0..7]
//   phase Y: outputs Y[ci=tm+32k, k=0..3][n=tn*8+0..7]
// smem: Th[128][64], Ck[128][132] (phi or g chunk), P[128][68],
//       redmax[8][64], redsum[8][64], run_max/run_sum/scale[64]
// ---------------------------------------------------------------------------
#define ATT_SMEM_FLOATS (8192 + 16896 + 8704 + 512 + 512 + 64 + 64 + 64)
#define ATT_SMEM_BYTES  (ATT_SMEM_FLOATS * 4)

__global__ __launch_bounds__(256, 1) void attn_kernel()
{
    extern __shared__ float sm[];
    float* Th      = sm;                 // [128][64]
    float* Ck      = Th + 8192;          // [128][132]
    float* P       = Ck + 16896;         // [128][68]
    float* redmax  = P + 8704;           // [8][64]
    float* redsum  = redmax + 512;       // [8][64]
    float* run_max = redsum + 512;       // [64]
    float* run_sum = run_max + 64;       // [64]
    float* scale_s = run_sum + 64;       // [64]

    int b = blockIdx.y, n0 = blockIdx.x * 64;
    int tid = threadIdx.x;
    int lane = tid & 31, wrp = tid >> 5;
    const float* thb = g_theta + b * (CI * NN);
    const float* phb = g_phip  + b * (CI * MM);
    const float* gpb = g_gp    + b * (CI * MM);

    // load theta tile [128ci][64n]
#pragma unroll
    for (int t = 0; t < 8; t++) {
        int id = tid + t * 256;
        int ci = id >> 4, s = id & 15;
        *(float4*)&Th[ci * 64 + s * 4] = *(const float4*)&thb[ci * NN + n0 + s * 4];
    }
    if (tid < 64) { run_max[tid] = -1e30f; run_sum[tid] = 0.f; }

    float4 pf[16];
    // prefetch phi chunk 0 and store
#pragma unroll
    for (int t = 0; t < 16; t++) {
        int id = tid + t * 256; int ci = id >> 5, s = id & 31;
        pf[t] = *(const float4*)&phb[ci * MM + s * 4];
    }
#pragma unroll
    for (int t = 0; t < 16; t++) {
        int id = tid + t * 256; int ci = id >> 5, s = id & 31;
        *(float4*)&Ck[ci * 132 + s * 4] = pf[t];
    }
    __syncthreads();

    int tn = tid & 7, tm = tid >> 3;
    int nl = tn * 8, ml = tm * 4;

    u64 accY[4][4] = {};   // [k(ci)][n-pair]

    for (int mc = 0; mc < 8; mc++) {
        // prefetch g chunk mc (consumed after S compute)
#pragma unroll
        for (int t = 0; t < 16; t++) {
            int id = tid + t * 256; int ci = id >> 5, s = id & 31;
            pf[t] = *(const float4*)&gpb[ci * MM + mc * 128 + s * 4];
        }

        // ---- S chunk: S[4m][8n] ----
        u64 accS[4][4] = {};
#pragma unroll 2
        for (int ci = 0; ci < CI; ci++) {
            float4 a0 = *(float4*)&Th[ci * 64 + nl];
            float4 a1 = *(float4*)&Th[ci * 64 + nl + 4];
            float4 p  = *(float4*)&Ck[ci * 132 + ml];
            u64 a01 = pack2(a0.x, a0.y), a23 = pack2(a0.z, a0.w);
            u64 a45 = pack2(a1.x, a1.y), a67 = pack2(a1.z, a1.w);
            u64 d;
            d = pack2(p.x, p.x); fma2(accS[0][0], a01, d); fma2(accS[0][1], a23, d);
                                 fma2(accS[0][2], a45, d); fma2(accS[0][3], a67, d);
            d = pack2(p.y, p.y); fma2(accS[1][0], a01, d); fma2(accS[1][1], a23, d);
                                 fma2(accS[1][2], a45, d); fma2(accS[1][3], a67, d);
            d = pack2(p.z, p.z); fma2(accS[2][0], a01, d); fma2(accS[2][1], a23, d);
                                 fma2(accS[2][2], a45, d); fma2(accS[2][3], a67, d);
            d = pack2(p.w, p.w); fma2(accS[3][0], a01, d); fma2(accS[3][1], a23, d);
                                 fma2(accS[3][2], a45, d); fma2(accS[3][3], a67, d);
        }
        float sarr[4][8];
#pragma unroll
        for (int mi = 0; mi < 4; mi++)
#pragma unroll
            for (int jp = 0; jp < 4; jp++) {
                float2 v = unpack2(accS[mi][jp]);
                sarr[mi][jp * 2] = v.x; sarr[mi][jp * 2 + 1] = v.y;
            }

        // chunk max per n (8 per thread), reduce over tm within warp then smem
        float lmax[8];
#pragma unroll
        for (int j = 0; j < 8; j++) {
            float m0 = fmaxf(sarr[0][j], sarr[1][j]);
            float m1 = fmaxf(sarr[2][j], sarr[3][j]);
            lmax[j] = fmaxf(m0, m1);
        }
#pragma unroll
        for (int j = 0; j < 8; j++) {
            lmax[j] = fmaxf(lmax[j], __shfl_xor_sync(0xffffffffu, lmax[j], 8));
            lmax[j] = fmaxf(lmax[j], __shfl_xor_sync(0xffffffffu, lmax[j], 16));
        }
        if (lane < 8) {
#pragma unroll
            for (int j = 0; j < 8; j++) redmax[wrp * 64 + nl + j] = lmax[j];
        }
        __syncthreads();   // redmax visible; all done reading Ck(phi)

        // STS g chunk
#pragma unroll
        for (int t = 0; t < 16; t++) {
            int id = tid + t * 256; int ci = id >> 5, s = id & 31;
            *(float4*)&Ck[ci * 132 + s * 4] = pf[t];
        }
        if (tid < 64) {
            int n = tid;
            float m8 = redmax[n];
#pragma unroll
            for (int w = 1; w < 8; w++) m8 = fmaxf(m8, redmax[w * 64 + n]);
            float old = run_max[n];
            float nw  = fmaxf(old, m8);
            float sc  = fast_exp(old - nw);
            run_max[n] = nw; scale_s[n] = sc;
            run_sum[n] = run_sum[n] * sc;
        }
        __syncthreads();   // Ck(g), run_max, scale visible

        // exp + write P + rescale accY + partial sums
        float rm_j[8], sc_j[8];
#pragma unroll
        for (int j = 0; j < 8; j++) { rm_j[j] = run_max[nl + j]; sc_j[j] = scale_s[nl + j]; }
        float lsum[8] = {0, 0, 0, 0, 0, 0, 0, 0};
#pragma unroll
        for (int mi = 0; mi < 4; mi++) {
#pragma unroll
            for (int j = 0; j < 8; j++) {
                float e = fast_exp(sarr[mi][j] - rm_j[j]);
                sarr[mi][j] = e;
                lsum[j] += e;
            }
            *(float4*)&P[(ml + mi) * 68 + nl] =
                make_float4(sarr[mi][0], sarr[mi][1], sarr[mi][2], sarr[mi][3]);
            *(float4*)&P[(ml + mi) * 68 + nl + 4] =
                make_float4(sarr[mi][4], sarr[mi][5], sarr[mi][6], sarr[mi][7]);
        }
#pragma unroll
        for (int k = 0; k < 4; k++)
#pragma unroll
            for (int jp = 0; jp < 4; jp++) {
                float2 v = unpack2(accY[k][jp]);
                v.x *= sc_j[jp * 2]; v.y *= sc_j[jp * 2 + 1];
                accY[k][jp] = pack2(v.x, v.y);
            }
#pragma unroll
        for (int j = 0; j < 8; j++) {
            lsum[j] += __shfl_xor_sync(0xffffffffu, lsum[j], 8);
            lsum[j] += __shfl_xor_sync(0xffffffffu, lsum[j], 16);
        }
        if (lane < 8) {
#pragma unroll
            for (int j = 0; j < 8; j++) redsum[wrp * 64 + nl + j] = lsum[j];
        }
        __syncthreads();   // P + redsum visible
        if (tid < 64) {
            int n = tid;
            float s8 = redsum[n];
#pragma unroll
            for (int w = 1; w < 8; w++) s8 += redsum[w * 64 + n];
            run_sum[n] += s8;
        }

        // prefetch phi chunk mc+1 (consumed next iteration)
        if (mc < 7) {
#pragma unroll
            for (int t = 0; t < 16; t++) {
                int id = tid + t * 256; int ci = id >> 5, s = id & 31;
                pf[t] = *(const float4*)&phb[ci * MM + (mc + 1) * 128 + s * 4];
            }
        }

        // ---- Y += P * G ----
#pragma unroll 4
        for (int m = 0; m < 128; m++) {
            float4 p0 = *(float4*)&P[m * 68 + nl];
            float4 p1 = *(float4*)&P[m * 68 + nl + 4];
            float g0 = Ck[tm * 132 + m];
            float g1 = Ck[(tm + 32) * 132 + m];
            float g2 = Ck[(tm + 64) * 132 + m];
            float g3 = Ck[(tm + 96) * 132 + m];
            u64 pp01 = pack2(p0.x, p0.y), pp23 = pack2(p0.z, p0.w);
            u64 pp45 = pack2(p1.x, p1.y), pp67 = pack2(p1.z, p1.w);
            u64 d;
            d = pack2(g0, g0); fma2(accY[0][0], pp01, d); fma2(accY[0][1], pp23, d);
                               fma2(accY[0][2], pp45, d); fma2(accY[0][3], pp67, d);
            d = pack2(g1, g1); fma2(accY[1][0], pp01, d); fma2(accY[1][1], pp23, d);
                               fma2(accY[1][2], pp45, d); fma2(accY[1][3], pp67, d);
            d = pack2(g2, g2); fma2(accY[2][0], pp01, d); fma2(accY[2][1], pp23, d);
                               fma2(accY[2][2], pp45, d); fma2(accY[2][3], pp67, d);
            d = pack2(g3, g3); fma2(accY[3][0], pp01, d); fma2(accY[3][1], pp23, d);
                               fma2(accY[3][2], pp45, d); fma2(accY[3][3], pp67, d);
        }
        __syncthreads();   // done reading Ck(g) and P
        if (mc < 7) {
#pragma unroll
            for (int t = 0; t < 16; t++) {
                int id = tid + t * 256; int ci = id >> 5, s = id & 31;
                *(float4*)&Ck[ci * 132 + s * 4] = pf[t];
            }
        }
        __syncthreads();   // next phi chunk visible
    }

    // epilogue: normalize by 1/run_sum and store
    float inv[8];
#pragma unroll
    for (int j = 0; j < 8; j++) inv[j] = 1.0f / run_sum[nl + j];
    float* yb = g_y + b * (CI * NN);
#pragma unroll
    for (int k = 0; k < 4; k++) {
        int ci = tm + 32 * k;
        float2 v0 = unpack2(accY[k][0]), v1 = unpack2(accY[k][1]);
        float2 v2 = unpack2(accY[k][2]), v3 = unpack2(accY[k][3]);
        *(float4*)&yb[ci * NN + n0 + nl] =
            make_float4(v0.x * inv[0], v0.y * inv[1], v1.x * inv[2], v1.y * inv[3]);
        *(float4*)&yb[ci * NN + n0 + nl + 4] =
            make_float4(v2.x * inv[4], v2.y * inv[5], v3.x * inv[6], v3.y * inv[7]);
    }
}

// ---------------------------------------------------------------------------
// K3: output projection GEMM (double-buffered) + deterministic BN partials.
// ---------------------------------------------------------------------------
__global__ __launch_bounds__(256) void wproj_kernel(
    const float* __restrict__ w, const float* __restrict__ bias)
{
    __shared__ float ws[2][16][64];
    __shared__ float xs[2][16][64];
    int b = blockIdx.z, o0 = blockIdx.y * 64, n0 = blockIdx.x * 64;
    const float* xb = g_y + b * CI * NN;
    float* ob = g_z + b * CC * NN;
    int tid = threadIdx.x, ty = tid >> 4, tx = tid & 15;
    int rr = tid >> 2, ss = tid & 3;
    u64 acc[4][2] = {};

    {
        float4 wv = *(const float4*)&w[(o0 + rr) * CI + ss * 4];
        float4 xv = *(const float4*)&xb[ty * NN + n0 + tx * 4];
        ws[0][ss * 4 + 0][rr] = wv.x; ws[0][ss * 4 + 1][rr] = wv.y;
        ws[0][ss * 4 + 2][rr] = wv.z; ws[0][ss * 4 + 3][rr] = wv.w;
        *(float4*)&xs[0][ty][tx * 4] = xv;
    }
    int cur = 0;
    for (int kt = 0; kt < 8; kt++) {
        __syncthreads();
        float4 wv2, xv2;
        if (kt < 7) {
            wv2 = *(const float4*)&w[(o0 + rr) * CI + (kt + 1) * 16 + ss * 4];
            xv2 = *(const float4*)&xb[((kt + 1) * 16 + ty) * NN + n0 + tx * 4];
        }
#pragma unroll
        for (int k = 0; k < 16; k++) {
            float4 av = *(float4*)&ws[cur][k][ty * 4];
            float4 bv = *(float4*)&xs[cur][k][tx * 4];
            u64 b01 = pack2(bv.x, bv.y), b23 = pack2(bv.z, bv.w);
            u64 d;
            d = pack2(av.x, av.x); fma2(acc[0][0], d, b01); fma2(acc[0][1], d, b23);
            d = pack2(av.y, av.y); fma2(acc[1][0], d, b01); fma2(acc[1][1], d, b23);
            d = pack2(av.z, av.z); fma2(acc[2][0], d, b01); fma2(acc[2][1], d, b23);
            d = pack2(av.w, av.w); fma2(acc[3][0], d, b01); fma2(acc[3][1], d, b23);
        }
        if (kt < 7) {
            int nx = cur ^ 1;
            ws[nx][ss * 4 + 0][rr] = wv2.x; ws[nx][ss * 4 + 1][rr] = wv2.y;
            ws[nx][ss * 4 + 2][rr] = wv2.z; ws[nx][ss * 4 + 3][rr] = wv2.w;
            *(float4*)&xs[nx][ty][tx * 4] = xv2;
            cur = nx;
        }
    }
#pragma unroll
    for (int oi = 0; oi < 4; oi++) {
        int o = o0 + ty * 4 + oi;
        float bv = bias[o];
        float2 p0 = unpack2(acc[oi][0]), p1 = unpack2(acc[oi][1]);
        float v0 = p0.x + bv, v1 = p0.y + bv, v2 = p1.x + bv, v3 = p1.y + bv;
        *(float4*)&ob[o * NN + n0 + tx * 4] = make_float4(v0, v1, v2, v3);
        float s  = v0 + v1 + v2 + v3;
        float s2 = v0 * v0 + v1 * v1 + v2 * v2 + v3 * v3;
#pragma unroll
        for (int off = 8; off > 0; off >>= 1) {
            s  += __shfl_xor_sync(0xffffffffu, s,  off);
            s2 += __shfl_xor_sync(0xffffffffu, s2, off);
        }
        if (tx == 0) {
            int slot = b * 64 + blockIdx.x;
            g_psum  [o * 512 + slot] = s;
            g_psumsq[o * 512 + slot] = s2;
        }
    }
}

// ---------------------------------------------------------------------------
// K4: finalize BN coefficients (deterministic).
// ---------------------------------------------------------------------------
__global__ void bnfin_kernel(const float* __restrict__ gamma,
                             const float* __restrict__ beta)
{
    int c = threadIdx.x;
    float s = 0.f, s2 = 0.f;
    for (int j = 0; j < 512; j++) { s += g_psum[c * 512 + j]; s2 += g_psumsq[c * 512 + j]; }
    const float inv_n = 1.0f / 32768.0f;
    float mean = s * inv_n;
    float var  = s2 * inv_n - mean * mean;
    float inv  = rsqrtf(var + 1e-5f);
    float a = gamma[c] * inv;
    g_bna[c] = a;
    g_bnb[c] = beta[c] - mean * a;
}

// ---------------------------------------------------------------------------
// K5: out = x + z * a[c] + b[c]
// ---------------------------------------------------------------------------
__global__ __launch_bounds__(256) void final_kernel(
    const float* __restrict__ x, float* __restrict__ out)
{
    int idx = blockIdx.x * 256 + threadIdx.x;
    int e = idx << 2;
    int c = (e >> 12) & 255;
    float4 xv = *(const float4*)(x + e);
    float4 zv = *((const float4*)g_z + idx);
    float a = g_bna[c], bb = g_bnb[c];
    float4 o;
    o.x = fmaf(zv.x, a, bb) + xv.x;
    o.y = fmaf(zv.y, a, bb) + xv.y;
    o.z = fmaf(zv.z, a, bb) + xv.z;
    o.w = fmaf(zv.w, a, bb) + xv.w;
    *(float4*)(out + e) = o;
}

// ---------------------------------------------------------------------------
extern "C" void kernel_launch(void* const* d_in, const int* in_sizes, int n_in,
                              void* d_out, int out_size)
{
    const float* x     = (const float*)d_in[0];
    const float* tw    = (const float*)d_in[1];
    const float* tb    = (const float*)d_in[2];
    const float* pw    = (const float*)d_in[3];
    const float* pb    = (const float*)d_in[4];
    const float* gw    = (const float*)d_in[5];
    const float* gbv   = (const float*)d_in[6];
    const float* Ww    = (const float*)d_in[7];
    const float* Wb    = (const float*)d_in[8];
    const float* gamma = (const float*)d_in[9];
    const float* beta  = (const float*)d_in[10];
    float* out = (float*)d_out;

    cudaFuncSetAttribute(attn_kernel,
                         cudaFuncAttributeMaxDynamicSharedMemorySize, ATT_SMEM_BYTES);

    proj_kernel<<<dim3(64, 6, 8), 256>>>(x, tw, tb, pw, pb, gw, gbv);
    pool_kernel<<<4096, 256>>>();
    attn_kernel<<<dim3(64, 8), 256, ATT_SMEM_BYTES>>>();
    wproj_kernel<<<dim3(64, 4, 8), 256>>>(Ww, Wb);
    bnfin_kernel<<<1, 256>>>(gamma, beta);
    final_kernel<<<8192, 256>>>(x, out);
}

// round 7
// speedup vs baseline: 1.6816x; 1.6816x over previous
#include <cuda_runtime.h>
#include <cuda_bf16.h>
#include <cstdint>

// ---------------------------------------------------------------------------
// NonLocalBlock: B=8, C=256, Ci=128, H=W=64, N=4096, M=1024
// Attention on mma.sync bf16x3 (sm_100-legal HMMA); rest SIMT fp32.
// ---------------------------------------------------------------------------

#define NB 8
#define CC 256
#define CI 128
#define NN 4096
#define MM 1024

typedef unsigned long long u64;

// ----------------------- SIMT helpers --------------------------------------
__device__ __forceinline__ u64 pack2(float lo, float hi) {
    u64 r; asm("mov.b64 %0, {%1, %2};" : "=l"(r) : "f"(lo), "f"(hi)); return r;
}
__device__ __forceinline__ void fma2(u64& d, u64 a, u64 b) {
    asm("fma.rn.f32x2 %0, %1, %2, %0;" : "+l"(d) : "l"(a), "l"(b));
}
__device__ __forceinline__ float2 unpack2(u64 v) {
    float2 f; asm("mov.b64 {%0, %1}, %2;" : "=f"(f.x), "=f"(f.y) : "l"(v)); return f;
}

__device__ __forceinline__ float fast_exp(float x) {
    float y = x * 1.44269504088896340736f;
    y = fmaxf(y, -126.0f);
    float k = floorf(y);
    float f = y - k;
    const float c1 = 0.6931471805599453f, c2 = 0.2402265069591007f,
                c3 = 0.05550410866482158f, c4 = 0.009618129107628477f,
                c5 = 0.0013333558146428443f, c6 = 1.540353039338161e-4f,
                c7 = 1.52527338040598e-5f;
    float p = fmaf(c7, f, c6);
    p = fmaf(p, f, c5); p = fmaf(p, f, c4); p = fmaf(p, f, c3);
    p = fmaf(p, f, c2); p = fmaf(p, f, c1); p = fmaf(p, f, 1.0f);
    int ik = (int)k;
    float s = __int_as_float((ik + 127) << 23);
    return p * s;
}

// ----------------------- tensor-core helpers --------------------------------
__device__ __forceinline__ uint32_t smem_u32(const void* p) {
    uint32_t a;
    asm("{ .reg .u64 t; cvta.to.shared.u64 t, %1; cvt.u32.u64 %0, t; }" : "=r"(a) : "l"(p));
    return a;
}
__device__ __forceinline__ void ldm4(uint32_t* r, uint32_t addr) {
    asm volatile("ldmatrix.sync.aligned.m8n8.x4.shared.b16 {%0,%1,%2,%3}, [%4];"
        : "=r"(r[0]), "=r"(r[1]), "=r"(r[2]), "=r"(r[3]) : "r"(addr));
}
__device__ __forceinline__ void mma_bf16(float* c, const uint32_t* a,
                                         uint32_t b0, uint32_t b1) {
    asm volatile(
        "mma.sync.aligned.m16n8k16.row.col.f32.bf16.bf16.f32 "
        "{%0,%1,%2,%3}, {%4,%5,%6,%7}, {%8,%9}, {%0,%1,%2,%3};"
        : "+f"(c[0]), "+f"(c[1]), "+f"(c[2]), "+f"(c[3])
        : "r"(a[0]), "r"(a[1]), "r"(a[2]), "r"(a[3]), "r"(b0), "r"(b1));
}
__device__ __forceinline__ void cpa16(uint32_t dst, const void* src) {
    asm volatile("cp.async.cg.shared.global [%0], [%1], 16;" :: "r"(dst), "l"(src));
}
#define CPA_COMMIT() asm volatile("cp.async.commit_group;" ::: "memory")
#define CPA_WAIT0()  asm volatile("cp.async.wait_group 0;" ::: "memory")
#define CPA_WAIT1()  asm volatile("cp.async.wait_group 1;" ::: "memory")

__device__ __forceinline__ uint32_t pack_bf16x2(float a, float b) {
    __nv_bfloat16 ha = __float2bfloat16_rn(a), hb = __float2bfloat16_rn(b);
    return ((uint32_t)__bfloat16_as_ushort(hb) << 16) | (uint32_t)__bfloat16_as_ushort(ha);
}

// ----------------------------- scratch ------------------------------------
__device__ float g_theta[NB * CI * NN];
__device__ float g_phif [NB * CI * NN];
__device__ float g_gf   [NB * CI * NN];
__device__ uint16_t g_phiH[NB * MM * CI];   // pooled phi split [b][m][ci] bf16
__device__ uint16_t g_phiL[NB * MM * CI];
__device__ uint16_t g_gHa [NB * CI * MM];   // pooled g split [b][ci][m] bf16
__device__ uint16_t g_gLa [NB * CI * MM];
__device__ float g_y    [NB * CI * NN];
__device__ float g_z    [NB * CC * NN];
__device__ float g_psum [CC * 512];
__device__ float g_psumsq[CC * 512];
__device__ float g_bna[CC], g_bnb[CC];

// ---------------------------------------------------------------------------
// K1: three projection GEMMs (double-buffered, SIMT fp32).
// ---------------------------------------------------------------------------
__global__ __launch_bounds__(256) void proj_kernel(
    const float* __restrict__ x,
    const float* __restrict__ tw, const float* __restrict__ tb,
    const float* __restrict__ pw, const float* __restrict__ pb,
    const float* __restrict__ gw, const float* __restrict__ gb)
{
    __shared__ float ws[2][16][64];
    __shared__ float xs[2][16][64];
    int b = blockIdx.z, ot = blockIdx.y, n0 = blockIdx.x * 64;
    const float *w, *bias; float* outb; int o0;
    if (ot < 2)      { w = tw; bias = tb; outb = g_theta; o0 = ot * 64; }
    else if (ot < 4) { w = pw; bias = pb; outb = g_phif;  o0 = (ot - 2) * 64; }
    else             { w = gw; bias = gb; outb = g_gf;    o0 = (ot - 4) * 64; }
    const float* xb = x + b * CC * NN;
    float* ob = outb + b * CI * NN;
    int tid = threadIdx.x, ty = tid >> 4, tx = tid & 15;
    int rr = tid >> 2, ss = tid & 3;
    u64 acc[4][2] = {};

    {
        float4 wv = *(const float4*)&w[(o0 + rr) * CC + ss * 4];
        float4 xv = *(const float4*)&xb[ty * NN + n0 + tx * 4];
        ws[0][ss * 4 + 0][rr] = wv.x; ws[0][ss * 4 + 1][rr] = wv.y;
        ws[0][ss * 4 + 2][rr] = wv.z; ws[0][ss * 4 + 3][rr] = wv.w;
        *(float4*)&xs[0][ty][tx * 4] = xv;
    }
    int cur = 0;
    for (int kt = 0; kt < 16; kt++) {
        __syncthreads();
        float4 wv2, xv2;
        if (kt < 15) {
            wv2 = *(const float4*)&w[(o0 + rr) * CC + (kt + 1) * 16 + ss * 4];
            xv2 = *(const float4*)&xb[((kt + 1) * 16 + ty) * NN + n0 + tx * 4];
        }
#pragma unroll
        for (int k = 0; k < 16; k++) {
            float4 av = *(float4*)&ws[cur][k][ty * 4];
            float4 bv = *(float4*)&xs[cur][k][tx * 4];
            u64 b01 = pack2(bv.x, bv.y), b23 = pack2(bv.z, bv.w);
            u64 d;
            d = pack2(av.x, av.x); fma2(acc[0][0], d, b01); fma2(acc[0][1], d, b23);
            d = pack2(av.y, av.y); fma2(acc[1][0], d, b01); fma2(acc[1][1], d, b23);
            d = pack2(av.z, av.z); fma2(acc[2][0], d, b01); fma2(acc[2][1], d, b23);
            d = pack2(av.w, av.w); fma2(acc[3][0], d, b01); fma2(acc[3][1], d, b23);
        }
        if (kt < 15) {
            int nx = cur ^ 1;
            ws[nx][ss * 4 + 0][rr] = wv2.x; ws[nx][ss * 4 + 1][rr] = wv2.y;
            ws[nx][ss * 4 + 2][rr] = wv2.z; ws[nx][ss * 4 + 3][rr] = wv2.w;
            *(float4*)&xs[nx][ty][tx * 4] = xv2;
            cur = nx;
        }
    }
#pragma unroll
    for (int oi = 0; oi < 4; oi++) {
        int o = o0 + ty * 4 + oi;
        float bv = bias[o];
        float2 p0 = unpack2(acc[oi][0]), p1 = unpack2(acc[oi][1]);
        *(float4*)&ob[o * NN + n0 + tx * 4] =
            make_float4(p0.x + bv, p0.y + bv, p1.x + bv, p1.y + bv);
    }
}

// ---------------------------------------------------------------------------
// K1b: 2x2 max-pool + bf16 hi/lo split.
// phi -> [b][m][ci] (scattered 2B); g -> [b][ci][m] (packed u32).
// ---------------------------------------------------------------------------
__global__ __launch_bounds__(256) void pool_kernel()
{
    int gid = blockIdx.x * 256 + threadIdx.x;
    bool isphi = (gid < 524288);
    int rid = isphi ? gid : gid - 524288;
    const float* src = isphi ? g_phif : g_gf;
    int wp = rid & 15, hp = (rid >> 4) & 31, bc = rid >> 9;
    const float* in = src + bc * 4096 + hp * 128 + wp * 4;
    float4 a = *(const float4*)in;
    float4 c = *(const float4*)(in + 64);
    float o0 = fmaxf(fmaxf(a.x, a.y), fmaxf(c.x, c.y));
    float o1 = fmaxf(fmaxf(a.z, a.w), fmaxf(c.z, c.w));
    int m0 = hp * 32 + wp * 2;
    __nv_bfloat16 h0 = __float2bfloat16_rn(o0);
    __nv_bfloat16 h1 = __float2bfloat16_rn(o1);
    __nv_bfloat16 l0 = __float2bfloat16_rn(o0 - __bfloat162float(h0));
    __nv_bfloat16 l1 = __float2bfloat16_rn(o1 - __bfloat162float(h1));
    int bb = bc >> 7, ci = bc & 127;
    if (isphi) {
        int base = (bb * MM + m0) * CI + ci;
        g_phiH[base]      = __bfloat16_as_ushort(h0);
        g_phiH[base + CI] = __bfloat16_as_ushort(h1);
        g_phiL[base]      = __bfloat16_as_ushort(l0);
        g_phiL[base + CI] = __bfloat16_as_ushort(l1);
    } else {
        int base = (bb * CI + ci) * MM + m0;   // even
        uint32_t hp2 = ((uint32_t)__bfloat16_as_ushort(h1) << 16) | __bfloat16_as_ushort(h0);
        uint32_t lp2 = ((uint32_t)__bfloat16_as_ushort(l1) << 16) | __bfloat16_as_ushort(l0);
        *(uint32_t*)&g_gHa[base] = hp2;
        *(uint32_t*)&g_gLa[base] = lp2;
    }
}

// ---------------------------------------------------------------------------
// K2: tensor-core attention (mma.sync bf16x3). CTA = (batch, 128 n-rows).
// smem rows padded to 136 bf16 (272B). Regions (each 34816B = [128][136]):
//   TH/TL: theta [n][ci] | PH/PL: phi [m][ci] then P [n][m] | GH/GL: g [ci][m]
// ---------------------------------------------------------------------------
#define PADB 272
#define TILE_B 34816
#define O_TH 0
#define O_TL 34816
#define O_PH 69632
#define O_PL 104448
#define O_GH 139264
#define O_GL 174080
#define O_INV 208896
#define ATT_SMEM 209920

__global__ __launch_bounds__(256, 1) void attn_mma_kernel()
{
    extern __shared__ char smem[];
    uint32_t sb = smem_u32(smem);
    int b = blockIdx.y, n0 = blockIdx.x * 128;
    int tid = threadIdx.x;
    int lane = tid & 31, wid = tid >> 5;
    int wrow = wid * 16;
    int qr = lane >> 2, qc = lane & 3;

    const float* thb = g_theta + b * (CI * NN);

    // ---- theta tile: load [ci][n] fp32, split, store [n][ci] hi/lo -------
#pragma unroll
    for (int j = 0; j < 16; j++) {
        int id = tid + j * 256;
        int ci = id >> 5, nq = (id & 31) * 4;
        float4 v = *(const float4*)&thb[ci * NN + n0 + nq];
#pragma unroll
        for (int e = 0; e < 4; e++) {
            float val = (&v.x)[e];
            __nv_bfloat16 h = __float2bfloat16_rn(val);
            __nv_bfloat16 l = __float2bfloat16_rn(val - __bfloat162float(h));
            int off = (nq + e) * PADB + ci * 2;
            *(uint16_t*)(smem + O_TH + off) = __bfloat16_as_ushort(h);
            *(uint16_t*)(smem + O_TL + off) = __bfloat16_as_ushort(l);
        }
    }

    // ---- chunk loaders (cp.async 16B) ------------------------------------
    // phi chunk mc: rows m (128), 16 segs of 16B -> PH/PL
    // g   chunk mc: rows ci (128), 16 segs     -> GH/GL
    auto load_phi = [&](int mc) {
#pragma unroll
        for (int j = 0; j < 8; j++) {
            int id = tid + j * 256;
            int row = id >> 4, seg = id & 15;
            int src = (b * MM + mc * 128 + row) * CI + seg * 8;
            uint32_t d = row * PADB + seg * 16;
            cpa16(sb + O_PH + d, &g_phiH[src]);
            cpa16(sb + O_PL + d, &g_phiL[src]);
        }
    };
    auto load_g = [&](int mc) {
#pragma unroll
        for (int j = 0; j < 8; j++) {
            int id = tid + j * 256;
            int row = id >> 4, seg = id & 15;
            int src = (b * CI + row) * MM + mc * 128 + seg * 8;
            uint32_t d = row * PADB + seg * 16;
            cpa16(sb + O_GH + d, &g_gHa[src]);
            cpa16(sb + O_GL + d, &g_gLa[src]);
        }
    };

    load_phi(0); CPA_COMMIT();
    load_g(0);   CPA_COMMIT();
    CPA_WAIT0();
    __syncthreads();

    float Yacc[16][4];
#pragma unroll
    for (int t = 0; t < 16; t++) { Yacc[t][0] = Yacc[t][1] = Yacc[t][2] = Yacc[t][3] = 0.f; }
    float rs0 = 0.f, rs1 = 0.f;

    // ldmatrix address components
    uint32_t a_row = (uint32_t)(wrow + (lane & 15));         // A: 16 rows
    uint32_t a_seg = (uint32_t)((lane >> 4) << 4);           // +0 / +16B
    uint32_t b_rlane = (uint32_t)(lane & 7);                 // B: 8 rows
    uint32_t b_seg = (uint32_t)((lane >> 3) << 4);           // +0/16/32/48B

    for (int mc = 0; mc < 8; mc++) {
        // ================= S = theta · phi^T =================
        float Sacc[16][4];
#pragma unroll
        for (int t = 0; t < 16; t++) { Sacc[t][0] = Sacc[t][1] = Sacc[t][2] = Sacc[t][3] = 0.f; }

#pragma unroll
        for (int kt = 0; kt < 8; kt += 2) {
            uint32_t aH[8], aL[8];
            uint32_t abase = a_row * PADB + kt * 32 + a_seg;
            ldm4(aH + 0, sb + O_TH + abase);
            ldm4(aH + 4, sb + O_TH + abase + 32);
            ldm4(aL + 0, sb + O_TL + abase);
            ldm4(aL + 4, sb + O_TL + abase + 32);
#pragma unroll
            for (int mt = 0; mt < 16; mt++) {
                uint32_t bH[4], bL[4];
                uint32_t bbase = (mt * 8 + b_rlane) * PADB + kt * 32 + b_seg;
                ldm4(bH, sb + O_PH + bbase);
                ldm4(bL, sb + O_PL + bbase);
                mma_bf16(Sacc[mt], aH + 0, bH[0], bH[1]);
                mma_bf16(Sacc[mt], aH + 0, bL[0], bL[1]);
                mma_bf16(Sacc[mt], aL + 0, bH[0], bH[1]);
                mma_bf16(Sacc[mt], aH + 4, bH[2], bH[3]);
                mma_bf16(Sacc[mt], aH + 4, bL[2], bL[3]);
                mma_bf16(Sacc[mt], aL + 4, bH[2], bH[3]);
            }
        }
        __syncthreads();   // all warps done reading phi buffer

        // ============ exp + split -> P (overwrites phi buffer) ============
        {
            int r0 = wrow + qr, r1 = r0 + 8;
#pragma unroll
            for (int mt = 0; mt < 16; mt++) {
                float e0 = fast_exp(Sacc[mt][0] - 20.0f);
                float e1 = fast_exp(Sacc[mt][1] - 20.0f);
                float e2 = fast_exp(Sacc[mt][2] - 20.0f);
                float e3 = fast_exp(Sacc[mt][3] - 20.0f);
                rs0 += e0 + e1; rs1 += e2 + e3;
                float h0 = __bfloat162float(__float2bfloat16_rn(e0));
                float h1 = __bfloat162float(__float2bfloat16_rn(e1));
                float h2 = __bfloat162float(__float2bfloat16_rn(e2));
                float h3 = __bfloat162float(__float2bfloat16_rn(e3));
                uint32_t off0 = r0 * PADB + mt * 16 + qc * 4;
                uint32_t off1 = r1 * PADB + mt * 16 + qc * 4;
                *(uint32_t*)(smem + O_PH + off0) = pack_bf16x2(h0, h1);
                *(uint32_t*)(smem + O_PH + off1) = pack_bf16x2(h2, h3);
                *(uint32_t*)(smem + O_PL + off0) = pack_bf16x2(e0 - h0, e1 - h1);
                *(uint32_t*)(smem + O_PL + off1) = pack_bf16x2(e2 - h2, e3 - h3);
            }
        }
        CPA_WAIT0();       // g chunk mc complete (issued last iteration)
        __syncthreads();   // P visible, g visible

        // ================= Y^T += g · P^T =================
#pragma unroll
        for (int kt = 0; kt < 8; kt += 2) {
            uint32_t aH[8], aL[8];
            uint32_t abase = a_row * PADB + kt * 32 + a_seg;
            ldm4(aH + 0, sb + O_GH + abase);
            ldm4(aH + 4, sb + O_GH + abase + 32);
            ldm4(aL + 0, sb + O_GL + abase);
            ldm4(aL + 4, sb + O_GL + abase + 32);
#pragma unroll
            for (int nt = 0; nt < 16; nt++) {
                uint32_t bH[4], bL[4];
                uint32_t bbase = (nt * 8 + b_rlane) * PADB + kt * 32 + b_seg;
                ldm4(bH, sb + O_PH + bbase);
                ldm4(bL, sb + O_PL + bbase);
                mma_bf16(Yacc[nt], aH + 0, bH[0], bH[1]);
                mma_bf16(Yacc[nt], aH + 0, bL[0], bL[1]);
                mma_bf16(Yacc[nt], aL + 0, bH[0], bH[1]);
                mma_bf16(Yacc[nt], aH + 4, bH[2], bH[3]);
                mma_bf16(Yacc[nt], aH + 4, bL[2], bL[3]);
                mma_bf16(Yacc[nt], aL + 4, bH[2], bH[3]);
            }
        }
        __syncthreads();   // P and g consumed

        if (mc < 7) {
            load_phi(mc + 1); CPA_COMMIT();
            load_g(mc + 1);   CPA_COMMIT();
            CPA_WAIT1();      // phi ready; g streams behind S+exp
            __syncthreads();
        }
    }

    // ---- rowsums -> inv[n] in smem ----------------------------------------
    rs0 += __shfl_xor_sync(0xffffffffu, rs0, 1);
    rs0 += __shfl_xor_sync(0xffffffffu, rs0, 2);
    rs1 += __shfl_xor_sync(0xffffffffu, rs1, 1);
    rs1 += __shfl_xor_sync(0xffffffffu, rs1, 2);
    float* invs = (float*)(smem + O_INV);
    if (qc == 0) {
        invs[wrow + qr]     = 1.0f / rs0;
        invs[wrow + qr + 8] = 1.0f / rs1;
    }
    __syncthreads();

    // ---- store Y^T: rows ci, cols n; normalize per n ----------------------
    float* yb = g_y + b * (CI * NN);
    int ci0 = wrow + qr;
#pragma unroll
    for (int nt = 0; nt < 16; nt++) {
        int n = nt * 8 + qc * 2;
        float in0 = invs[n], in1 = invs[n + 1];
        *(float2*)&yb[ci0 * NN + n0 + n] =
            make_float2(Yacc[nt][0] * in0, Yacc[nt][1] * in1);
        *(float2*)&yb[(ci0 + 8) * NN + n0 + n] =
            make_float2(Yacc[nt][2] * in0, Yacc[nt][3] * in1);
    }
}

// ---------------------------------------------------------------------------
// K3: output projection GEMM + deterministic BN partials (SIMT fp32).
// ---------------------------------------------------------------------------
__global__ __launch_bounds__(256) void wproj_kernel(
    const float* __restrict__ w, const float* __restrict__ bias)
{
    __shared__ float ws[2][16][64];
    __shared__ float xs[2][16][64];
    int b = blockIdx.z, o0 = blockIdx.y * 64, n0 = blockIdx.x * 64;
    const float* xb = g_y + b * CI * NN;
    float* ob = g_z + b * CC * NN;
    int tid = threadIdx.x, ty = tid >> 4, tx = tid & 15;
    int rr = tid >> 2, ss = tid & 3;
    u64 acc[4][2] = {};

    {
        float4 wv = *(const float4*)&w[(o0 + rr) * CI + ss * 4];
        float4 xv = *(const float4*)&xb[ty * NN + n0 + tx * 4];
        ws[0][ss * 4 + 0][rr] = wv.x; ws[0][ss * 4 + 1][rr] = wv.y;
        ws[0][ss * 4 + 2][rr] = wv.z; ws[0][ss * 4 + 3][rr] = wv.w;
        *(float4*)&xs[0][ty][tx * 4] = xv;
    }
    int cur = 0;
    for (int kt = 0; kt < 8; kt++) {
        __syncthreads();
        float4 wv2, xv2;
        if (kt < 7) {
            wv2 = *(const float4*)&w[(o0 + rr) * CI + (kt + 1) * 16 + ss * 4];
            xv2 = *(const float4*)&xb[((kt + 1) * 16 + ty) * NN + n0 + tx * 4];
        }
#pragma unroll
        for (int k = 0; k < 16; k++) {
            float4 av = *(float4*)&ws[cur][k][ty * 4];
            float4 bv = *(float4*)&xs[cur][k][tx * 4];
            u64 b01 = pack2(bv.x, bv.y), b23 = pack2(bv.z, bv.w);
            u64 d;
            d = pack2(av.x, av.x); fma2(acc[0][0], d, b01); fma2(acc[0][1], d, b23);
            d = pack2(av.y, av.y); fma2(acc[1][0], d, b01); fma2(acc[1][1], d, b23);
            d = pack2(av.z, av.z); fma2(acc[2][0], d, b01); fma2(acc[2][1], d, b23);
            d = pack2(av.w, av.w); fma2(acc[3][0], d, b01); fma2(acc[3][1], d, b23);
        }
        if (kt < 7) {
            int nx = cur ^ 1;
            ws[nx][ss * 4 + 0][rr] = wv2.x; ws[nx][ss * 4 + 1][rr] = wv2.y;
            ws[nx][ss * 4 + 2][rr] = wv2.z; ws[nx][ss * 4 + 3][rr] = wv2.w;
            *(float4*)&xs[nx][ty][tx * 4] = xv2;
            cur = nx;
        }
    }
#pragma unroll
    for (int oi = 0; oi < 4; oi++) {
        int o = o0 + ty * 4 + oi;
        float bv = bias[o];
        float2 p0 = unpack2(acc[oi][0]), p1 = unpack2(acc[oi][1]);
        float v0 = p0.x + bv, v1 = p0.y + bv, v2 = p1.x + bv, v3 = p1.y + bv;
        *(float4*)&ob[o * NN + n0 + tx * 4] = make_float4(v0, v1, v2, v3);
        float s  = v0 + v1 + v2 + v3;
        float s2 = v0 * v0 + v1 * v1 + v2 * v2 + v3 * v3;
#pragma unroll
        for (int off = 8; off > 0; off >>= 1) {
            s  += __shfl_xor_sync(0xffffffffu, s,  off);
            s2 += __shfl_xor_sync(0xffffffffu, s2, off);
        }
        if (tx == 0) {
            int slot = b * 64 + blockIdx.x;
            g_psum  [o * 512 + slot] = s;
            g_psumsq[o * 512 + slot] = s2;
        }
    }
}

// ---------------------------------------------------------------------------
__global__ void bnfin_kernel(const float* __restrict__ gamma,
                             const float* __restrict__ beta)
{
    int c = threadIdx.x;
    float s = 0.f, s2 = 0.f;
    for (int j = 0; j < 512; j++) { s += g_psum[c * 512 + j]; s2 += g_psumsq[c * 512 + j]; }
    const float inv_n = 1.0f / 32768.0f;
    float mean = s * inv_n;
    float var  = s2 * inv_n - mean * mean;
    float inv  = rsqrtf(var + 1e-5f);
    float a = gamma[c] * inv;
    g_bna[c] = a;
    g_bnb[c] = beta[c] - mean * a;
}

// ---------------------------------------------------------------------------
__global__ __launch_bounds__(256) void final_kernel(
    const float* __restrict__ x, float* __restrict__ out)
{
    int idx = blockIdx.x * 256 + threadIdx.x;
    int e = idx << 2;
    int c = (e >> 12) & 255;
    float4 xv = *(const float4*)(x + e);
    float4 zv = *((const float4*)g_z + idx);
    float a = g_bna[c], bb = g_bnb[c];
    float4 o;
    o.x = fmaf(zv.x, a, bb) + xv.x;
    o.y = fmaf(zv.y, a, bb) + xv.y;
    o.z = fmaf(zv.z, a, bb) + xv.z;
    o.w = fmaf(zv.w, a, bb) + xv.w;
    *(float4*)(out + e) = o;
}

// ---------------------------------------------------------------------------
extern "C" void kernel_launch(void* const* d_in, const int* in_sizes, int n_in,
                              void* d_out, int out_size)
{
    const float* x     = (const float*)d_in[0];
    const float* tw    = (const float*)d_in[1];
    const float* tb    = (const float*)d_in[2];
    const float* pw    = (const float*)d_in[3];
    const float* pb    = (const float*)d_in[4];
    const float* gw    = (const float*)d_in[5];
    const float* gbv   = (const float*)d_in[6];
    const float* Ww    = (const float*)d_in[7];
    const float* Wb    = (const float*)d_in[8];
    const float* gamma = (const float*)d_in[9];
    const float* beta  = (const float*)d_in[10];
    float* out = (float*)d_out;

    cudaFuncSetAttribute(attn_mma_kernel,
                         cudaFuncAttributeMaxDynamicSharedMemorySize, ATT_SMEM);

    proj_kernel<<<dim3(64, 6, 8), 256>>>(x, tw, tb, pw, pb, gw, gbv);
    pool_kernel<<<4096, 256>>>();
    attn_mma_kernel<<<dim3(32, 8), 256, ATT_SMEM>>>();
    wproj_kernel<<<dim3(64, 4, 8), 256>>>(Ww, Wb);
    bnfin_kernel<<<1, 256>>>(gamma, beta);
    final_kernel<<<8192, 256>>>(x, out);
}

// round 10
// speedup vs baseline: 2.3354x; 1.3889x over previous
#include <cuda_runtime.h>
#include <cuda_bf16.h>
#include <cstdint>

// ---------------------------------------------------------------------------
// NonLocalBlock: B=8, C=256, Ci=128, H=W=64, N=4096, M=1024
// ALL GEMMs on mma.sync bf16x3 (sm_100-legal HMMA).
// ---------------------------------------------------------------------------

#define NB 8
#define CC 256
#define CI 128
#define NN 4096
#define MM 1024

typedef unsigned long long u64;

__device__ __forceinline__ float fast_exp(float x) {
    float y = x * 1.44269504088896340736f;
    y = fmaxf(y, -126.0f);
    float k = floorf(y);
    float f = y - k;
    const float c1 = 0.6931471805599453f, c2 = 0.2402265069591007f,
                c3 = 0.05550410866482158f, c4 = 0.009618129107628477f,
                c5 = 0.0013333558146428443f, c6 = 1.540353039338161e-4f,
                c7 = 1.52527338040598e-5f;
    float p = fmaf(c7, f, c6);
    p = fmaf(p, f, c5); p = fmaf(p, f, c4); p = fmaf(p, f, c3);
    p = fmaf(p, f, c2); p = fmaf(p, f, c1); p = fmaf(p, f, 1.0f);
    int ik = (int)k;
    float s = __int_as_float((ik + 127) << 23);
    return p * s;
}

// ----------------------- tensor-core helpers --------------------------------
__device__ __forceinline__ uint32_t smem_u32(const void* p) {
    uint32_t a;
    asm("{ .reg .u64 t; cvta.to.shared.u64 t, %1; cvt.u32.u64 %0, t; }" : "=r"(a) : "l"(p));
    return a;
}
__device__ __forceinline__ void ldm4(uint32_t* r, uint32_t addr) {
    asm volatile("ldmatrix.sync.aligned.m8n8.x4.shared.b16 {%0,%1,%2,%3}, [%4];"
        : "=r"(r[0]), "=r"(r[1]), "=r"(r[2]), "=r"(r[3]) : "r"(addr));
}
__device__ __forceinline__ void mma_bf16(float* c, const uint32_t* a,
                                         uint32_t b0, uint32_t b1) {
    asm volatile(
        "mma.sync.aligned.m16n8k16.row.col.f32.bf16.bf16.f32 "
        "{%0,%1,%2,%3}, {%4,%5,%6,%7}, {%8,%9}, {%0,%1,%2,%3};"
        : "+f"(c[0]), "+f"(c[1]), "+f"(c[2]), "+f"(c[3])
        : "r"(a[0]), "r"(a[1]), "r"(a[2]), "r"(a[3]), "r"(b0), "r"(b1));
}
__device__ __forceinline__ void cpa16(uint32_t dst, const void* src) {
    asm volatile("cp.async.cg.shared.global [%0], [%1], 16;" :: "r"(dst), "l"(src));
}
#define CPA_COMMIT() asm volatile("cp.async.commit_group;" ::: "memory")
#define CPA_WAIT0()  asm volatile("cp.async.wait_group 0;" ::: "memory")
#define CPA_WAIT1()  asm volatile("cp.async.wait_group 1;" ::: "memory")

__device__ __forceinline__ uint32_t pack_bf16x2(float a, float b) {
    __nv_bfloat16 ha = __float2bfloat16_rn(a), hb = __float2bfloat16_rn(b);
    return ((uint32_t)__bfloat16_as_ushort(hb) << 16) | (uint32_t)__bfloat16_as_ushort(ha);
}

// ----------------------------- scratch ------------------------------------
__device__ float g_theta[NB * CI * NN];
__device__ float g_phif [NB * CI * NN];
__device__ float g_gf   [NB * CI * NN];
__device__ uint16_t g_phiH[NB * MM * CI];   // pooled phi split [b][m][ci]
__device__ uint16_t g_phiL[NB * MM * CI];
__device__ uint16_t g_gHa [NB * CI * MM];   // pooled g split [b][ci][m]
__device__ uint16_t g_gLa [NB * CI * MM];
__device__ uint16_t g_xTH [NB * NN * CC];   // x^T split [b][n][c]
__device__ uint16_t g_xTL [NB * NN * CC];
__device__ uint16_t g_yTH [NB * NN * CI];   // y^T split [b][n][ci]
__device__ uint16_t g_yTL [NB * NN * CI];
__device__ uint16_t g_wsH [131072];         // tw|pw|gw (3x32768) then Ww (32768)
__device__ uint16_t g_wsL [131072];
__device__ float g_y    [NB * CI * NN];
__device__ float g_z    [NB * CC * NN];
__device__ float g_psum [CC * 512];
__device__ float g_psumsq[CC * 512];
__device__ float g_bna[CC], g_bnb[CC];

// ---------------------------------------------------------------------------
// xsplit: transpose + bf16 hi/lo split. x [b][256][4096] -> g_xTH/L [b][n][256].
// grid (128 ntile, 8 ctile, 8 b), 256 threads, 32x32 tile.
// ---------------------------------------------------------------------------
__global__ __launch_bounds__(256) void xsplit_kernel(const float* __restrict__ src)
{
    __shared__ float t[32][33];
    int b = blockIdx.z, c0 = blockIdx.y * 32, n0 = blockIdx.x * 32;
    int tid = threadIdx.x;
    int cl = tid >> 3, ng = (tid & 7) * 4;
    float4 v = *(const float4*)&src[((u64)b * CC + c0 + cl) * NN + n0 + ng];
    t[cl][ng] = v.x; t[cl][ng + 1] = v.y; t[cl][ng + 2] = v.z; t[cl][ng + 3] = v.w;
    __syncthreads();
    int nl = tid >> 3, cg = (tid & 7) * 4;
    uint16_t hs[4], ls[4];
#pragma unroll
    for (int e = 0; e < 4; e++) {
        float val = t[cg + e][nl];
        __nv_bfloat16 h = __float2bfloat16_rn(val);
        __nv_bfloat16 l = __float2bfloat16_rn(val - __bfloat162float(h));
        hs[e] = __bfloat16_as_ushort(h); ls[e] = __bfloat16_as_ushort(l);
    }
    u64 di = ((u64)b * NN + n0 + nl) * CC + c0 + cg;
    *(uint2*)&g_xTH[di] = *(uint2*)hs;
    *(uint2*)&g_xTL[di] = *(uint2*)ls;
}

// ---------------------------------------------------------------------------
// ysplit: same for y: g_y [b][128][4096] -> g_yTH/L [b][n][128].
// grid (128 ntile, 4 ctile, 8 b).
// ---------------------------------------------------------------------------
__global__ __launch_bounds__(256) void ysplit_kernel()
{
    __shared__ float t[32][33];
    int b = blockIdx.z, c0 = blockIdx.y * 32, n0 = blockIdx.x * 32;
    int tid = threadIdx.x;
    int cl = tid >> 3, ng = (tid & 7) * 4;
    float4 v = *(const float4*)&g_y[((u64)b * CI + c0 + cl) * NN + n0 + ng];
    t[cl][ng] = v.x; t[cl][ng + 1] = v.y; t[cl][ng + 2] = v.z; t[cl][ng + 3] = v.w;
    __syncthreads();
    int nl = tid >> 3, cg = (tid & 7) * 4;
    uint16_t hs[4], ls[4];
#pragma unroll
    for (int e = 0; e < 4; e++) {
        float val = t[cg + e][nl];
        __nv_bfloat16 h = __float2bfloat16_rn(val);
        __nv_bfloat16 l = __float2bfloat16_rn(val - __bfloat162float(h));
        hs[e] = __bfloat16_as_ushort(h); ls[e] = __bfloat16_as_ushort(l);
    }
    u64 di = ((u64)b * NN + n0 + nl) * CI + c0 + cg;
    *(uint2*)&g_yTH[di] = *(uint2*)hs;
    *(uint2*)&g_yTL[di] = *(uint2*)ls;
}

// ---------------------------------------------------------------------------
// wsplit: flat split of all weights into g_wsH/g_wsL.
// ---------------------------------------------------------------------------
__global__ __launch_bounds__(256) void wsplit_kernel(
    const float* __restrict__ tw, const float* __restrict__ pw,
    const float* __restrict__ gw, const float* __restrict__ Ww)
{
    int idx = blockIdx.x * 256 + threadIdx.x;   // 131072
    const float* src; int off;
    if (idx < 32768)       { src = tw; off = idx; }
    else if (idx < 65536)  { src = pw; off = idx - 32768; }
    else if (idx < 98304)  { src = gw; off = idx - 65536; }
    else                   { src = Ww; off = idx - 98304; }
    float v = src[off];
    __nv_bfloat16 h = __float2bfloat16_rn(v);
    __nv_bfloat16 l = __float2bfloat16_rn(v - __bfloat162float(h));
    g_wsH[idx] = __bfloat16_as_ushort(h);
    g_wsL[idx] = __bfloat16_as_ushort(l);
}

// ---------------------------------------------------------------------------
// proj_mma: out[o,n] = sum_c w[o,c] x[c,n] + bias[o], bf16x3 mma.
// CTA = 128o x 128n, K=256 (two 128-chunks). grid (32 ntile, 3 proj, 8 b).
// smem: AH AL BH BL each [128][272B].
// ---------------------------------------------------------------------------
#define PADB 272
#define TILE_B 34816
#define PRJ_SMEM (4 * TILE_B)

__global__ __launch_bounds__(256, 1) void proj_mma_kernel(
    const float* __restrict__ tb, const float* __restrict__ pb,
    const float* __restrict__ gb)
{
    extern __shared__ char smem[];
    uint32_t sb = smem_u32(smem);
    const uint32_t O_AH = 0, O_AL = TILE_B, O_BH = 2 * TILE_B, O_BL = 3 * TILE_B;
    int b = blockIdx.z, pj = blockIdx.y, n0 = blockIdx.x * 128;
    int tid = threadIdx.x, lane = tid & 31, wid = tid >> 5;
    int wrow = wid * 16, qr = lane >> 2, qc = lane & 3;

    const uint16_t* wH = g_wsH + pj * 32768;
    const uint16_t* wL = g_wsL + pj * 32768;
    const float* bias = (pj == 0) ? tb : (pj == 1) ? pb : gb;
    float* outb = ((pj == 0) ? g_theta : (pj == 1) ? g_phif : g_gf) + (u64)b * CI * NN;

    uint32_t a_row = (uint32_t)(wrow + (lane & 15));
    uint32_t a_seg = (uint32_t)((lane >> 4) << 4);
    uint32_t b_rlane = (uint32_t)(lane & 7);
    uint32_t b_seg = (uint32_t)((lane >> 3) << 4);

    float Dacc[16][4];
#pragma unroll
    for (int t = 0; t < 16; t++) { Dacc[t][0] = Dacc[t][1] = Dacc[t][2] = Dacc[t][3] = 0.f; }

    for (int kc = 0; kc < 2; kc++) {
#pragma unroll
        for (int j = 0; j < 8; j++) {
            int id = tid + j * 256;
            int row = id >> 4, seg = id & 15;
            uint32_t d = row * PADB + seg * 16;
            int wsrc = row * 256 + kc * 128 + seg * 8;
            u64 xsrc = ((u64)b * NN + n0 + row) * CC + kc * 128 + seg * 8;
            cpa16(sb + O_AH + d, &wH[wsrc]);
            cpa16(sb + O_AL + d, &wL[wsrc]);
            cpa16(sb + O_BH + d, &g_xTH[xsrc]);
            cpa16(sb + O_BL + d, &g_xTL[xsrc]);
        }
        CPA_COMMIT(); CPA_WAIT0();
        __syncthreads();

#pragma unroll
        for (int kt = 0; kt < 8; kt += 2) {
            uint32_t aH[8], aL[8];
            uint32_t abase = a_row * PADB + kt * 32 + a_seg;
            ldm4(aH + 0, sb + O_AH + abase);
            ldm4(aH + 4, sb + O_AH + abase + 32);
            ldm4(aL + 0, sb + O_AL + abase);
            ldm4(aL + 4, sb + O_AL + abase + 32);
#pragma unroll
            for (int mt = 0; mt < 16; mt++) {
                uint32_t bH[4], bL[4];
                uint32_t bbase = (mt * 8 + b_rlane) * PADB + kt * 32 + b_seg;
                ldm4(bH, sb + O_BH + bbase);
                ldm4(bL, sb + O_BL + bbase);
                mma_bf16(Dacc[mt], aH + 0, bH[0], bH[1]);
                mma_bf16(Dacc[mt], aH + 0, bL[0], bL[1]);
                mma_bf16(Dacc[mt], aL + 0, bH[0], bH[1]);
                mma_bf16(Dacc[mt], aH + 4, bH[2], bH[3]);
                mma_bf16(Dacc[mt], aH + 4, bL[2], bL[3]);
                mma_bf16(Dacc[mt], aL + 4, bH[2], bH[3]);
            }
        }
        __syncthreads();
    }

    int o0 = wrow + qr;
    float bv0 = bias[o0], bv1 = bias[o0 + 8];
#pragma unroll
    for (int mt = 0; mt < 16; mt++) {
        int n = n0 + mt * 8 + qc * 2;
        *(float2*)&outb[(u64)o0 * NN + n] =
            make_float2(Dacc[mt][0] + bv0, Dacc[mt][1] + bv0);
        *(float2*)&outb[(u64)(o0 + 8) * NN + n] =
            make_float2(Dacc[mt][2] + bv1, Dacc[mt][3] + bv1);
    }
}

// ---------------------------------------------------------------------------
// K1b: 2x2 max-pool + bf16 hi/lo split.
// ---------------------------------------------------------------------------
__global__ __launch_bounds__(256) void pool_kernel()
{
    int gid = blockIdx.x * 256 + threadIdx.x;
    bool isphi = (gid < 524288);
    int rid = isphi ? gid : gid - 524288;
    const float* src = isphi ? g_phif : g_gf;
    int wp = rid & 15, hp = (rid >> 4) & 31, bc = rid >> 9;
    const float* in = src + (u64)bc * 4096 + hp * 128 + wp * 4;
    float4 a = *(const float4*)in;
    float4 c = *(const float4*)(in + 64);
    float o0 = fmaxf(fmaxf(a.x, a.y), fmaxf(c.x, c.y));
    float o1 = fmaxf(fmaxf(a.z, a.w), fmaxf(c.z, c.w));
    int m0 = hp * 32 + wp * 2;
    __nv_bfloat16 h0 = __float2bfloat16_rn(o0);
    __nv_bfloat16 h1 = __float2bfloat16_rn(o1);
    __nv_bfloat16 l0 = __float2bfloat16_rn(o0 - __bfloat162float(h0));
    __nv_bfloat16 l1 = __float2bfloat16_rn(o1 - __bfloat162float(h1));
    int bb = bc >> 7, ci = bc & 127;
    if (isphi) {
        int base = (bb * MM + m0) * CI + ci;
        g_phiH[base]      = __bfloat16_as_ushort(h0);
        g_phiH[base + CI] = __bfloat16_as_ushort(h1);
        g_phiL[base]      = __bfloat16_as_ushort(l0);
        g_phiL[base + CI] = __bfloat16_as_ushort(l1);
    } else {
        int base = (bb * CI + ci) * MM + m0;
        uint32_t hp2 = ((uint32_t)__bfloat16_as_ushort(h1) << 16) | __bfloat16_as_ushort(h0);
        uint32_t lp2 = ((uint32_t)__bfloat16_as_ushort(l1) << 16) | __bfloat16_as_ushort(l0);
        *(uint32_t*)&g_gHa[base] = hp2;
        *(uint32_t*)&g_gLa[base] = lp2;
    }
}

// ---------------------------------------------------------------------------
// K2: tensor-core attention (validated R7).
// ---------------------------------------------------------------------------
#define O_TH 0
#define O_TL 34816
#define O_PH 69632
#define O_PL 104448
#define O_GH 139264
#define O_GL 174080
#define O_INV 208896
#define ATT_SMEM 209920

__global__ __launch_bounds__(256, 1) void attn_mma_kernel()
{
    extern __shared__ char smem[];
    uint32_t sb = smem_u32(smem);
    int b = blockIdx.y, n0 = blockIdx.x * 128;
    int tid = threadIdx.x;
    int lane = tid & 31, wid = tid >> 5;
    int wrow = wid * 16;
    int qr = lane >> 2, qc = lane & 3;

    const float* thb = g_theta + (u64)b * (CI * NN);

#pragma unroll
    for (int j = 0; j < 16; j++) {
        int id = tid + j * 256;
        int ci = id >> 5, nq = (id & 31) * 4;
        float4 v = *(const float4*)&thb[(u64)ci * NN + n0 + nq];
#pragma unroll
        for (int e = 0; e < 4; e++) {
            float val = (&v.x)[e];
            __nv_bfloat16 h = __float2bfloat16_rn(val);
            __nv_bfloat16 l = __float2bfloat16_rn(val - __bfloat162float(h));
            int off = (nq + e) * PADB + ci * 2;
            *(uint16_t*)(smem + O_TH + off) = __bfloat16_as_ushort(h);
            *(uint16_t*)(smem + O_TL + off) = __bfloat16_as_ushort(l);
        }
    }

    auto load_phi = [&](int mc) {
#pragma unroll
        for (int j = 0; j < 8; j++) {
            int id = tid + j * 256;
            int row = id >> 4, seg = id & 15;
            int src = (b * MM + mc * 128 + row) * CI + seg * 8;
            uint32_t d = row * PADB + seg * 16;
            cpa16(sb + O_PH + d, &g_phiH[src]);
            cpa16(sb + O_PL + d, &g_phiL[src]);
        }
    };
    auto load_g = [&](int mc) {
#pragma unroll
        for (int j = 0; j < 8; j++) {
            int id = tid + j * 256;
            int row = id >> 4, seg = id & 15;
            int src = (b * CI + row) * MM + mc * 128 + seg * 8;
            uint32_t d = row * PADB + seg * 16;
            cpa16(sb + O_GH + d, &g_gHa[src]);
            cpa16(sb + O_GL + d, &g_gLa[src]);
        }
    };

    load_phi(0); CPA_COMMIT();
    load_g(0);   CPA_COMMIT();
    CPA_WAIT0();
    __syncthreads();

    float Yacc[16][4];
#pragma unroll
    for (int t = 0; t < 16; t++) { Yacc[t][0] = Yacc[t][1] = Yacc[t][2] = Yacc[t][3] = 0.f; }
    float rs0 = 0.f, rs1 = 0.f;

    uint32_t a_row = (uint32_t)(wrow + (lane & 15));
    uint32_t a_seg = (uint32_t)((lane >> 4) << 4);
    uint32_t b_rlane = (uint32_t)(lane & 7);
    uint32_t b_seg = (uint32_t)((lane >> 3) << 4);

    for (int mc = 0; mc < 8; mc++) {
        float Sacc[16][4];
#pragma unroll
        for (int t = 0; t < 16; t++) { Sacc[t][0] = Sacc[t][1] = Sacc[t][2] = Sacc[t][3] = 0.f; }

#pragma unroll
        for (int kt = 0; kt < 8; kt += 2) {
            uint32_t aH[8], aL[8];
            uint32_t abase = a_row * PADB + kt * 32 + a_seg;
            ldm4(aH + 0, sb + O_TH + abase);
            ldm4(aH + 4, sb + O_TH + abase + 32);
            ldm4(aL + 0, sb + O_TL + abase);
            ldm4(aL + 4, sb + O_TL + abase + 32);
#pragma unroll
            for (int mt = 0; mt < 16; mt++) {
                uint32_t bH[4], bL[4];
                uint32_t bbase = (mt * 8 + b_rlane) * PADB + kt * 32 + b_seg;
                ldm4(bH, sb + O_PH + bbase);
                ldm4(bL, sb + O_PL + bbase);
                mma_bf16(Sacc[mt], aH + 0, bH[0], bH[1]);
                mma_bf16(Sacc[mt], aH + 0, bL[0], bL[1]);
                mma_bf16(Sacc[mt], aL + 0, bH[0], bH[1]);
                mma_bf16(Sacc[mt], aH + 4, bH[2], bH[3]);
                mma_bf16(Sacc[mt], aH + 4, bL[2], bL[3]);
                mma_bf16(Sacc[mt], aL + 4, bH[2], bH[3]);
            }
        }
        __syncthreads();

        {
            int r0 = wrow + qr, r1 = r0 + 8;
#pragma unroll
            for (int mt = 0; mt < 16; mt++) {
                float e0 = fast_exp(Sacc[mt][0] - 20.0f);
                float e1 = fast_exp(Sacc[mt][1] - 20.0f);
                float e2 = fast_exp(Sacc[mt][2] - 20.0f);
                float e3 = fast_exp(Sacc[mt][3] - 20.0f);
                rs0 += e0 + e1; rs1 += e2 + e3;
                float h0 = __bfloat162float(__float2bfloat16_rn(e0));
                float h1 = __bfloat162float(__float2bfloat16_rn(e1));
                float h2 = __bfloat162float(__float2bfloat16_rn(e2));
                float h3 = __bfloat162float(__float2bfloat16_rn(e3));
                uint32_t off0 = r0 * PADB + mt * 16 + qc * 4;
                uint32_t off1 = r1 * PADB + mt * 16 + qc * 4;
                *(uint32_t*)(smem + O_PH + off0) = pack_bf16x2(h0, h1);
                *(uint32_t*)(smem + O_PH + off1) = pack_bf16x2(h2, h3);
                *(uint32_t*)(smem + O_PL + off0) = pack_bf16x2(e0 - h0, e1 - h1);
                *(uint32_t*)(smem + O_PL + off1) = pack_bf16x2(e2 - h2, e3 - h3);
            }
        }
        CPA_WAIT0();
        __syncthreads();

#pragma unroll
        for (int kt = 0; kt < 8; kt += 2) {
            uint32_t aH[8], aL[8];
            uint32_t abase = a_row * PADB + kt * 32 + a_seg;
            ldm4(aH + 0, sb + O_GH + abase);
            ldm4(aH + 4, sb + O_GH + abase + 32);
            ldm4(aL + 0, sb + O_GL + abase);
            ldm4(aL + 4, sb + O_GL + abase + 32);
#pragma unroll
            for (int nt = 0; nt < 16; nt++) {
                uint32_t bH[4], bL[4];
                uint32_t bbase = (nt * 8 + b_rlane) * PADB + kt * 32 + b_seg;
                ldm4(bH, sb + O_PH + bbase);
                ldm4(bL, sb + O_PL + bbase);
                mma_bf16(Yacc[nt], aH + 0, bH[0], bH[1]);
                mma_bf16(Yacc[nt], aH + 0, bL[0], bL[1]);
                mma_bf16(Yacc[nt], aL + 0, bH[0], bH[1]);
                mma_bf16(Yacc[nt], aH + 4, bH[2], bH[3]);
                mma_bf16(Yacc[nt], aH + 4, bL[2], bL[3]);
                mma_bf16(Yacc[nt], aL + 4, bH[2], bH[3]);
            }
        }
        __syncthreads();

        if (mc < 7) {
            load_phi(mc + 1); CPA_COMMIT();
            load_g(mc + 1);   CPA_COMMIT();
            CPA_WAIT1();
            __syncthreads();
        }
    }

    rs0 += __shfl_xor_sync(0xffffffffu, rs0, 1);
    rs0 += __shfl_xor_sync(0xffffffffu, rs0, 2);
    rs1 += __shfl_xor_sync(0xffffffffu, rs1, 1);
    rs1 += __shfl_xor_sync(0xffffffffu, rs1, 2);
    float* invs = (float*)(smem + O_INV);
    if (qc == 0) {
        invs[wrow + qr]     = 1.0f / rs0;
        invs[wrow + qr + 8] = 1.0f / rs1;
    }
    __syncthreads();

    float* yb = g_y + (u64)b * (CI * NN);
    int ci0 = wrow + qr;
#pragma unroll
    for (int nt = 0; nt < 16; nt++) {
        int n = nt * 8 + qc * 2;
        float in0 = invs[n], in1 = invs[n + 1];
        *(float2*)&yb[(u64)ci0 * NN + n0 + n] =
            make_float2(Yacc[nt][0] * in0, Yacc[nt][1] * in1);
        *(float2*)&yb[(u64)(ci0 + 8) * NN + n0 + n] =
            make_float2(Yacc[nt][2] * in0, Yacc[nt][3] * in1);
    }
}

// ---------------------------------------------------------------------------
// wproj_mma: z = Ww @ y + Wb, bf16x3 mma, K=128, + deterministic BN partials.
// CTA = 128o x 128n. grid (32 ntile, 2 otile, 8 b). slots = b*32 + ntile.
// ---------------------------------------------------------------------------
__global__ __launch_bounds__(256, 1) void wproj_mma_kernel(
    const float* __restrict__ bias)
{
    extern __shared__ char smem[];
    uint32_t sb = smem_u32(smem);
    const uint32_t O_AH = 0, O_AL = TILE_B, O_BH = 2 * TILE_B, O_BL = 3 * TILE_B;
    int b = blockIdx.z, o0 = blockIdx.y * 128, n0 = blockIdx.x * 128;
    int tid = threadIdx.x, lane = tid & 31, wid = tid >> 5;
    int wrow = wid * 16, qr = lane >> 2, qc = lane & 3;

#pragma unroll
    for (int j = 0; j < 8; j++) {
        int id = tid + j * 256;
        int row = id >> 4, seg = id & 15;
        uint32_t d = row * PADB + seg * 16;
        int wsrc = 98304 + (o0 + row) * 128 + seg * 8;
        u64 ysrc = ((u64)b * NN + n0 + row) * CI + seg * 8;
        cpa16(sb + O_AH + d, &g_wsH[wsrc]);
        cpa16(sb + O_AL + d, &g_wsL[wsrc]);
        cpa16(sb + O_BH + d, &g_yTH[ysrc]);
        cpa16(sb + O_BL + d, &g_yTL[ysrc]);
    }
    CPA_COMMIT(); CPA_WAIT0();
    __syncthreads();

    uint32_t a_row = (uint32_t)(wrow + (lane & 15));
    uint32_t a_seg = (uint32_t)((lane >> 4) << 4);
    uint32_t b_rlane = (uint32_t)(lane & 7);
    uint32_t b_seg = (uint32_t)((lane >> 3) << 4);

    float Dacc[16][4];
#pragma unroll
    for (int t = 0; t < 16; t++) { Dacc[t][0] = Dacc[t][1] = Dacc[t][2] = Dacc[t][3] = 0.f; }

#pragma unroll
    for (int kt = 0; kt < 8; kt += 2) {
        uint32_t aH[8], aL[8];
        uint32_t abase = a_row * PADB + kt * 32 + a_seg;
        ldm4(aH + 0, sb + O_AH + abase);
        ldm4(aH + 4, sb + O_AH + abase + 32);
        ldm4(aL + 0, sb + O_AL + abase);
        ldm4(aL + 4, sb + O_AL + abase + 32);
#pragma unroll
        for (int mt = 0; mt < 16; mt++) {
            uint32_t bH[4], bL[4];
            uint32_t bbase = (mt * 8 + b_rlane) * PADB + kt * 32 + b_seg;
            ldm4(bH, sb + O_BH + bbase);
            ldm4(bL, sb + O_BL + bbase);
            mma_bf16(Dacc[mt], aH + 0, bH[0], bH[1]);
            mma_bf16(Dacc[mt], aH + 0, bL[0], bL[1]);
            mma_bf16(Dacc[mt], aL + 0, bH[0], bH[1]);
            mma_bf16(Dacc[mt], aH + 4, bH[2], bH[3]);
            mma_bf16(Dacc[mt], aH + 4, bL[2], bL[3]);
            mma_bf16(Dacc[mt], aL + 4, bH[2], bH[3]);
        }
    }

    int og0 = o0 + wrow + qr, og1 = og0 + 8;
    float bv0 = bias[og0], bv1 = bias[og1];
    float* ob = g_z + (u64)b * CC * NN;
    float s0 = 0.f, q0 = 0.f, s1 = 0.f, q1 = 0.f;
#pragma unroll
    for (int mt = 0; mt < 16; mt++) {
        int n = n0 + mt * 8 + qc * 2;
        float v0 = Dacc[mt][0] + bv0, v1 = Dacc[mt][1] + bv0;
        float v2 = Dacc[mt][2] + bv1, v3 = Dacc[mt][3] + bv1;
        *(float2*)&ob[(u64)og0 * NN + n] = make_float2(v0, v1);
        *(float2*)&ob[(u64)og1 * NN + n] = make_float2(v2, v3);
        s0 += v0 + v1; q0 += v0 * v0 + v1 * v1;
        s1 += v2 + v3; q1 += v2 * v2 + v3 * v3;
    }
    s0 += __shfl_xor_sync(0xffffffffu, s0, 1);
    s0 += __shfl_xor_sync(0xffffffffu, s0, 2);
    q0 += __shfl_xor_sync(0xffffffffu, q0, 1);
    q0 += __shfl_xor_sync(0xffffffffu, q0, 2);
    s1 += __shfl_xor_sync(0xffffffffu, s1, 1);
    s1 += __shfl_xor_sync(0xffffffffu, s1, 2);
    q1 += __shfl_xor_sync(0xffffffffu, q1, 1);
    q1 += __shfl_xor_sync(0xffffffffu, q1, 2);
    if (qc == 0) {
        int slot = b * 32 + blockIdx.x;   // [0,256)
        g_psum  [og0 * 256 + slot] = s0;
        g_psumsq[og0 * 256 + slot] = q0;
        g_psum  [og1 * 256 + slot] = s1;
        g_psumsq[og1 * 256 + slot] = q1;
    }
}

// ---------------------------------------------------------------------------
__global__ void bnfin_kernel(const float* __restrict__ gamma,
                             const float* __restrict__ beta)
{
    int c = threadIdx.x;
    float s = 0.f, s2 = 0.f;
    for (int j = 0; j < 256; j++) { s += g_psum[c * 256 + j]; s2 += g_psumsq[c * 256 + j]; }
    const float inv_n = 1.0f / 32768.0f;
    float mean = s * inv_n;
    float var  = s2 * inv_n - mean * mean;
    float inv  = rsqrtf(var + 1e-5f);
    float a = gamma[c] * inv;
    g_bna[c] = a;
    g_bnb[c] = beta[c] - mean * a;
}

// ---------------------------------------------------------------------------
__global__ __launch_bounds__(256) void final_kernel(
    const float* __restrict__ x, float* __restrict__ out)
{
    int idx = blockIdx.x * 256 + threadIdx.x;
    u64 e = (u64)idx << 2;
    int c = (int)((e >> 12) & 255);
    float4 xv = *(const float4*)(x + e);
    float4 zv = *((const float4*)g_z + idx);
    float a = g_bna[c], bb = g_bnb[c];
    float4 o;
    o.x = fmaf(zv.x, a, bb) + xv.x;
    o.y = fmaf(zv.y, a, bb) + xv.y;
    o.z = fmaf(zv.z, a, bb) + xv.z;
    o.w = fmaf(zv.w, a, bb) + xv.w;
    *(float4*)(out + e) = o;
}

// ---------------------------------------------------------------------------
extern "C" void kernel_launch(void* const* d_in, const int* in_sizes, int n_in,
                              void* d_out, int out_size)
{
    const float* x     = (const float*)d_in[0];
    const float* tw    = (const float*)d_in[1];
    const float* tb    = (const float*)d_in[2];
    const float* pw    = (const float*)d_in[3];
    const float* pb    = (const float*)d_in[4];
    const float* gw    = (const float*)d_in[5];
    const float* gbv   = (const float*)d_in[6];
    const float* Ww    = (const float*)d_in[7];
    const float* Wb    = (const float*)d_in[8];
    const float* gamma = (const float*)d_in[9];
    const float* beta  = (const float*)d_in[10];
    float* out = (float*)d_out;

    cudaFuncSetAttribute(attn_mma_kernel,
                         cudaFuncAttributeMaxDynamicSharedMemorySize, ATT_SMEM);
    cudaFuncSetAttribute(proj_mma_kernel,
                         cudaFuncAttributeMaxDynamicSharedMemorySize, PRJ_SMEM);
    cudaFuncSetAttribute(wproj_mma_kernel,
                         cudaFuncAttributeMaxDynamicSharedMemorySize, PRJ_SMEM);

    xsplit_kernel<<<dim3(128, 8, 8), 256>>>(x);
    wsplit_kernel<<<512, 256>>>(tw, pw, gw, Ww);
    proj_mma_kernel<<<dim3(32, 3, 8), 256, PRJ_SMEM>>>(tb, pb, gbv);
    pool_kernel<<<4096, 256>>>();
    attn_mma_kernel<<<dim3(32, 8), 256, ATT_SMEM>>>();
    ysplit_kernel<<<dim3(128, 4, 8), 256>>>();
    wproj_mma_kernel<<<dim3(32, 2, 8), 256, PRJ_SMEM>>>(Wb);
    bnfin_kernel<<<1, 256>>>(gamma, beta);
    final_kernel<<<8192, 256>>>(x, out);
}

// round 11
// speedup vs baseline: 2.5425x; 1.0887x over previous
#include <cuda_runtime.h>
#include <cuda_bf16.h>
#include <cstdint>

// ---------------------------------------------------------------------------
// NonLocalBlock: B=8, C=256, Ci=128, H=W=64, N=4096, M=1024
// ALL GEMMs on mma.sync bf16x3; pool fused into proj epilogue; y-split fused
// into attn epilogue; exp via MUFU ex2.
// ---------------------------------------------------------------------------

#define NB 8
#define CC 256
#define CI 128
#define NN 4096
#define MM 1024

typedef unsigned long long u64;

// exp(s - 20) via MUFU: 2^(s*log2e - 20*log2e)
__device__ __forceinline__ float exp_s(float s) {
    float r;
    float t = fmaf(s, 1.4426950408889634f, -28.853900817779268f);
    asm("ex2.approx.f32 %0, %1;" : "=f"(r) : "f"(t));
    return r;
}

// ----------------------- tensor-core helpers --------------------------------
__device__ __forceinline__ uint32_t smem_u32(const void* p) {
    uint32_t a;
    asm("{ .reg .u64 t; cvta.to.shared.u64 t, %1; cvt.u32.u64 %0, t; }" : "=r"(a) : "l"(p));
    return a;
}
__device__ __forceinline__ void ldm4(uint32_t* r, uint32_t addr) {
    asm volatile("ldmatrix.sync.aligned.m8n8.x4.shared.b16 {%0,%1,%2,%3}, [%4];"
        : "=r"(r[0]), "=r"(r[1]), "=r"(r[2]), "=r"(r[3]) : "r"(addr));
}
__device__ __forceinline__ void mma_bf16(float* c, const uint32_t* a,
                                         uint32_t b0, uint32_t b1) {
    asm volatile(
        "mma.sync.aligned.m16n8k16.row.col.f32.bf16.bf16.f32 "
        "{%0,%1,%2,%3}, {%4,%5,%6,%7}, {%8,%9}, {%0,%1,%2,%3};"
        : "+f"(c[0]), "+f"(c[1]), "+f"(c[2]), "+f"(c[3])
        : "r"(a[0]), "r"(a[1]), "r"(a[2]), "r"(a[3]), "r"(b0), "r"(b1));
}
__device__ __forceinline__ void cpa16(uint32_t dst, const void* src) {
    asm volatile("cp.async.cg.shared.global [%0], [%1], 16;" :: "r"(dst), "l"(src));
}
#define CPA_COMMIT() asm volatile("cp.async.commit_group;" ::: "memory")
#define CPA_WAIT0()  asm volatile("cp.async.wait_group 0;" ::: "memory")
#define CPA_WAIT1()  asm volatile("cp.async.wait_group 1;" ::: "memory")

__device__ __forceinline__ uint32_t pack_bf16x2(float a, float b) {
    __nv_bfloat16 ha = __float2bfloat16_rn(a), hb = __float2bfloat16_rn(b);
    return ((uint32_t)__bfloat16_as_ushort(hb) << 16) | (uint32_t)__bfloat16_as_ushort(ha);
}

// ----------------------------- scratch ------------------------------------
__device__ float g_theta[NB * CI * NN];
__device__ uint16_t g_phiH[NB * MM * CI];   // pooled phi split [b][m][ci]
__device__ uint16_t g_phiL[NB * MM * CI];
__device__ uint16_t g_gHa [NB * CI * MM];   // pooled g split [b][ci][m]
__device__ uint16_t g_gLa [NB * CI * MM];
__device__ uint16_t g_xTH [NB * NN * CC];   // x^T split [b][n][c]
__device__ uint16_t g_xTL [NB * NN * CC];
__device__ uint16_t g_yTH [NB * NN * CI];   // y^T split [b][n][ci]
__device__ uint16_t g_yTL [NB * NN * CI];
__device__ uint16_t g_wsH [131072];         // tw|pw|gw (3x32768) then Ww (32768)
__device__ uint16_t g_wsL [131072];
__device__ float g_z    [NB * CC * NN];
__device__ float g_psum [CC * 256];
__device__ float g_psumsq[CC * 256];
__device__ float g_bna[CC], g_bnb[CC];

// ---------------------------------------------------------------------------
// xsplit: transpose + bf16 hi/lo split. x [b][256][4096] -> g_xTH/L [b][n][256].
// ---------------------------------------------------------------------------
__global__ __launch_bounds__(256) void xsplit_kernel(const float* __restrict__ src)
{
    __shared__ float t[32][33];
    int b = blockIdx.z, c0 = blockIdx.y * 32, n0 = blockIdx.x * 32;
    int tid = threadIdx.x;
    int cl = tid >> 3, ng = (tid & 7) * 4;
    float4 v = *(const float4*)&src[((u64)b * CC + c0 + cl) * NN + n0 + ng];
    t[cl][ng] = v.x; t[cl][ng + 1] = v.y; t[cl][ng + 2] = v.z; t[cl][ng + 3] = v.w;
    __syncthreads();
    int nl = tid >> 3, cg = (tid & 7) * 4;
    uint16_t hs[4], ls[4];
#pragma unroll
    for (int e = 0; e < 4; e++) {
        float val = t[cg + e][nl];
        __nv_bfloat16 h = __float2bfloat16_rn(val);
        __nv_bfloat16 l = __float2bfloat16_rn(val - __bfloat162float(h));
        hs[e] = __bfloat16_as_ushort(h); ls[e] = __bfloat16_as_ushort(l);
    }
    u64 di = ((u64)b * NN + n0 + nl) * CC + c0 + cg;
    *(uint2*)&g_xTH[di] = *(uint2*)hs;
    *(uint2*)&g_xTL[di] = *(uint2*)ls;
}

// ---------------------------------------------------------------------------
// wsplit: flat split of all weights into g_wsH/g_wsL.
// ---------------------------------------------------------------------------
__global__ __launch_bounds__(256) void wsplit_kernel(
    const float* __restrict__ tw, const float* __restrict__ pw,
    const float* __restrict__ gw, const float* __restrict__ Ww)
{
    int idx = blockIdx.x * 256 + threadIdx.x;   // 131072
    const float* src; int off;
    if (idx < 32768)       { src = tw; off = idx; }
    else if (idx < 65536)  { src = pw; off = idx - 32768; }
    else if (idx < 98304)  { src = gw; off = idx - 65536; }
    else                   { src = Ww; off = idx - 98304; }
    float v = src[off];
    __nv_bfloat16 h = __float2bfloat16_rn(v);
    __nv_bfloat16 l = __float2bfloat16_rn(v - __bfloat162float(h));
    g_wsH[idx] = __bfloat16_as_ushort(h);
    g_wsL[idx] = __bfloat16_as_ushort(l);
}

// ---------------------------------------------------------------------------
// proj_mma: out[o,n] = sum_c w[o,c] x[c,n] + bias[o], bf16x3 mma.
// pj=0 (theta): store fp32 [ci][n]. pj=1,2 (phi/g): fused 2x2 maxpool +
// split-bf16 store to pooled layouts. CTA = 128o x 128n, K=256.
// n-tile 128 = image rows h=2t,2t+1: pool partners (c,c+1,c+64,c+65) are in
// the SAME thread at (mt, mt+8), cols qc*2, qc*2+1.
// ---------------------------------------------------------------------------
#define PADB 272
#define TILE_B 34816
#define PRJ_SMEM (4 * TILE_B)

__global__ __launch_bounds__(256, 1) void proj_mma_kernel(
    const float* __restrict__ tb, const float* __restrict__ pb,
    const float* __restrict__ gb)
{
    extern __shared__ char smem[];
    uint32_t sb = smem_u32(smem);
    const uint32_t O_AH = 0, O_AL = TILE_B, O_BH = 2 * TILE_B, O_BL = 3 * TILE_B;
    int b = blockIdx.z, pj = blockIdx.y, n0 = blockIdx.x * 128;
    int tid = threadIdx.x, lane = tid & 31, wid = tid >> 5;
    int wrow = wid * 16, qr = lane >> 2, qc = lane & 3;

    const uint16_t* wH = g_wsH + pj * 32768;
    const uint16_t* wL = g_wsL + pj * 32768;
    const float* bias = (pj == 0) ? tb : (pj == 1) ? pb : gb;

    uint32_t a_row = (uint32_t)(wrow + (lane & 15));
    uint32_t a_seg = (uint32_t)((lane >> 4) << 4);
    uint32_t b_rlane = (uint32_t)(lane & 7);
    uint32_t b_seg = (uint32_t)((lane >> 3) << 4);

    float Dacc[16][4];
#pragma unroll
    for (int t = 0; t < 16; t++) { Dacc[t][0] = Dacc[t][1] = Dacc[t][2] = Dacc[t][3] = 0.f; }

    for (int kc = 0; kc < 2; kc++) {
#pragma unroll
        for (int j = 0; j < 8; j++) {
            int id = tid + j * 256;
            int row = id >> 4, seg = id & 15;
            uint32_t d = row * PADB + seg * 16;
            int wsrc = row * 256 + kc * 128 + seg * 8;
            u64 xsrc = ((u64)b * NN + n0 + row) * CC + kc * 128 + seg * 8;
            cpa16(sb + O_AH + d, &wH[wsrc]);
            cpa16(sb + O_AL + d, &wL[wsrc]);
            cpa16(sb + O_BH + d, &g_xTH[xsrc]);
            cpa16(sb + O_BL + d, &g_xTL[xsrc]);
        }
        CPA_COMMIT(); CPA_WAIT0();
        __syncthreads();

#pragma unroll
        for (int kt = 0; kt < 8; kt += 2) {
            uint32_t aH[8], aL[8];
            uint32_t abase = a_row * PADB + kt * 32 + a_seg;
            ldm4(aH + 0, sb + O_AH + abase);
            ldm4(aH + 4, sb + O_AH + abase + 32);
            ldm4(aL + 0, sb + O_AL + abase);
            ldm4(aL + 4, sb + O_AL + abase + 32);
#pragma unroll
            for (int mt = 0; mt < 16; mt++) {
                uint32_t bH[4], bL[4];
                uint32_t bbase = (mt * 8 + b_rlane) * PADB + kt * 32 + b_seg;
                ldm4(bH, sb + O_BH + bbase);
                ldm4(bL, sb + O_BL + bbase);
                mma_bf16(Dacc[mt], aH + 0, bH[0], bH[1]);
                mma_bf16(Dacc[mt], aH + 0, bL[0], bL[1]);
                mma_bf16(Dacc[mt], aL + 0, bH[0], bH[1]);
                mma_bf16(Dacc[mt], aH + 4, bH[2], bH[3]);
                mma_bf16(Dacc[mt], aH + 4, bL[2], bL[3]);
                mma_bf16(Dacc[mt], aL + 4, bH[2], bH[3]);
            }
        }
        __syncthreads();
    }

    int o0 = wrow + qr;
    float bv0 = bias[o0], bv1 = bias[o0 + 8];

    if (pj == 0) {
        float* outb = g_theta + (u64)b * CI * NN;
#pragma unroll
        for (int mt = 0; mt < 16; mt++) {
            int n = n0 + mt * 8 + qc * 2;
            *(float2*)&outb[(u64)o0 * NN + n] =
                make_float2(Dacc[mt][0] + bv0, Dacc[mt][1] + bv0);
            *(float2*)&outb[(u64)(o0 + 8) * NN + n] =
                make_float2(Dacc[mt][2] + bv1, Dacc[mt][3] + bv1);
        }
    } else {
        uint16_t* dH = (pj == 1) ? g_phiH : g_gHa;
        uint16_t* dL = (pj == 1) ? g_phiL : g_gLa;
#pragma unroll
        for (int mt2 = 0; mt2 < 8; mt2++) {
            int m = blockIdx.x * 32 + mt2 * 4 + qc;
            float p0 = fmaxf(fmaxf(Dacc[mt2][0], Dacc[mt2][1]),
                             fmaxf(Dacc[mt2 + 8][0], Dacc[mt2 + 8][1])) + bv0;
            float p1 = fmaxf(fmaxf(Dacc[mt2][2], Dacc[mt2][3]),
                             fmaxf(Dacc[mt2 + 8][2], Dacc[mt2 + 8][3])) + bv1;
            __nv_bfloat16 h0 = __float2bfloat16_rn(p0);
            __nv_bfloat16 l0 = __float2bfloat16_rn(p0 - __bfloat162float(h0));
            __nv_bfloat16 h1 = __float2bfloat16_rn(p1);
            __nv_bfloat16 l1 = __float2bfloat16_rn(p1 - __bfloat162float(h1));
            u64 i0, i1;
            if (pj == 1) { i0 = ((u64)b * MM + m) * CI + o0; i1 = i0 + 8; }
            else         { i0 = ((u64)b * CI + o0) * MM + m; i1 = i0 + (u64)8 * MM; }
            dH[i0] = __bfloat16_as_ushort(h0); dL[i0] = __bfloat16_as_ushort(l0);
            dH[i1] = __bfloat16_as_ushort(h1); dL[i1] = __bfloat16_as_ushort(l1);
        }
    }
}

// ---------------------------------------------------------------------------
// K2: tensor-core attention. Epilogue writes y^T split-bf16 directly.
// ---------------------------------------------------------------------------
#define O_TH 0
#define O_TL 34816
#define O_PH 69632
#define O_PL 104448
#define O_GH 139264
#define O_GL 174080
#define O_INV 208896
#define ATT_SMEM 209920

__global__ __launch_bounds__(256, 1) void attn_mma_kernel()
{
    extern __shared__ char smem[];
    uint32_t sb = smem_u32(smem);
    int b = blockIdx.y, n0 = blockIdx.x * 128;
    int tid = threadIdx.x;
    int lane = tid & 31, wid = tid >> 5;
    int wrow = wid * 16;
    int qr = lane >> 2, qc = lane & 3;

    const float* thb = g_theta + (u64)b * (CI * NN);

#pragma unroll
    for (int j = 0; j < 16; j++) {
        int id = tid + j * 256;
        int ci = id >> 5, nq = (id & 31) * 4;
        float4 v = *(const float4*)&thb[(u64)ci * NN + n0 + nq];
#pragma unroll
        for (int e = 0; e < 4; e++) {
            float val = (&v.x)[e];
            __nv_bfloat16 h = __float2bfloat16_rn(val);
            __nv_bfloat16 l = __float2bfloat16_rn(val - __bfloat162float(h));
            int off = (nq + e) * PADB + ci * 2;
            *(uint16_t*)(smem + O_TH + off) = __bfloat16_as_ushort(h);
            *(uint16_t*)(smem + O_TL + off) = __bfloat16_as_ushort(l);
        }
    }

    auto load_phi = [&](int mc) {
#pragma unroll
        for (int j = 0; j < 8; j++) {
            int id = tid + j * 256;
            int row = id >> 4, seg = id & 15;
            int src = (b * MM + mc * 128 + row) * CI + seg * 8;
            uint32_t d = row * PADB + seg * 16;
            cpa16(sb + O_PH + d, &g_phiH[src]);
            cpa16(sb + O_PL + d, &g_phiL[src]);
        }
    };
    auto load_g = [&](int mc) {
#pragma unroll
        for (int j = 0; j < 8; j++) {
            int id = tid + j * 256;
            int row = id >> 4, seg = id & 15;
            int src = (b * CI + row) * MM + mc * 128 + seg * 8;
            uint32_t d = row * PADB + seg * 16;
            cpa16(sb + O_GH + d, &g_gHa[src]);
            cpa16(sb + O_GL + d, &g_gLa[src]);
        }
    };

    load_phi(0); CPA_COMMIT();
    load_g(0);   CPA_COMMIT();
    CPA_WAIT0();
    __syncthreads();

    float Yacc[16][4];
#pragma unroll
    for (int t = 0; t < 16; t++) { Yacc[t][0] = Yacc[t][1] = Yacc[t][2] = Yacc[t][3] = 0.f; }
    float rs0 = 0.f, rs1 = 0.f;

    uint32_t a_row = (uint32_t)(wrow + (lane & 15));
    uint32_t a_seg = (uint32_t)((lane >> 4) << 4);
    uint32_t b_rlane = (uint32_t)(lane & 7);
    uint32_t b_seg = (uint32_t)((lane >> 3) << 4);

    for (int mc = 0; mc < 8; mc++) {
        float Sacc[16][4];
#pragma unroll
        for (int t = 0; t < 16; t++) { Sacc[t][0] = Sacc[t][1] = Sacc[t][2] = Sacc[t][3] = 0.f; }

#pragma unroll
        for (int kt = 0; kt < 8; kt += 2) {
            uint32_t aH[8], aL[8];
            uint32_t abase = a_row * PADB + kt * 32 + a_seg;
            ldm4(aH + 0, sb + O_TH + abase);
            ldm4(aH + 4, sb + O_TH + abase + 32);
            ldm4(aL + 0, sb + O_TL + abase);
            ldm4(aL + 4, sb + O_TL + abase + 32);
#pragma unroll
            for (int mt = 0; mt < 16; mt++) {
                uint32_t bH[4], bL[4];
                uint32_t bbase = (mt * 8 + b_rlane) * PADB + kt * 32 + b_seg;
                ldm4(bH, sb + O_PH + bbase);
                ldm4(bL, sb + O_PL + bbase);
                mma_bf16(Sacc[mt], aH + 0, bH[0], bH[1]);
                mma_bf16(Sacc[mt], aH + 0, bL[0], bL[1]);
                mma_bf16(Sacc[mt], aL + 0, bH[0], bH[1]);
                mma_bf16(Sacc[mt], aH + 4, bH[2], bH[3]);
                mma_bf16(Sacc[mt], aH + 4, bL[2], bL[3]);
                mma_bf16(Sacc[mt], aL + 4, bH[2], bH[3]);
            }
        }
        __syncthreads();

        {
            int r0 = wrow + qr, r1 = r0 + 8;
#pragma unroll
            for (int mt = 0; mt < 16; mt++) {
                float e0 = exp_s(Sacc[mt][0]);
                float e1 = exp_s(Sacc[mt][1]);
                float e2 = exp_s(Sacc[mt][2]);
                float e3 = exp_s(Sacc[mt][3]);
                rs0 += e0 + e1; rs1 += e2 + e3;
                float h0 = __bfloat162float(__float2bfloat16_rn(e0));
                float h1 = __bfloat162float(__float2bfloat16_rn(e1));
                float h2 = __bfloat162float(__float2bfloat16_rn(e2));
                float h3 = __bfloat162float(__float2bfloat16_rn(e3));
                uint32_t off0 = r0 * PADB + mt * 16 + qc * 4;
                uint32_t off1 = r1 * PADB + mt * 16 + qc * 4;
                *(uint32_t*)(smem + O_PH + off0) = pack_bf16x2(h0, h1);
                *(uint32_t*)(smem + O_PH + off1) = pack_bf16x2(h2, h3);
                *(uint32_t*)(smem + O_PL + off0) = pack_bf16x2(e0 - h0, e1 - h1);
                *(uint32_t*)(smem + O_PL + off1) = pack_bf16x2(e2 - h2, e3 - h3);
            }
        }
        CPA_WAIT0();
        __syncthreads();

#pragma unroll
        for (int kt = 0; kt < 8; kt += 2) {
            uint32_t aH[8], aL[8];
            uint32_t abase = a_row * PADB + kt * 32 + a_seg;
            ldm4(aH + 0, sb + O_GH + abase);
            ldm4(aH + 4, sb + O_GH + abase + 32);
            ldm4(aL + 0, sb + O_GL + abase);
            ldm4(aL + 4, sb + O_GL + abase + 32);
#pragma unroll
            for (int nt = 0; nt < 16; nt++) {
                uint32_t bH[4], bL[4];
                uint32_t bbase = (nt * 8 + b_rlane) * PADB + kt * 32 + b_seg;
                ldm4(bH, sb + O_PH + bbase);
                ldm4(bL, sb + O_PL + bbase);
                mma_bf16(Yacc[nt], aH + 0, bH[0], bH[1]);
                mma_bf16(Yacc[nt], aH + 0, bL[0], bL[1]);
                mma_bf16(Yacc[nt], aL + 0, bH[0], bH[1]);
                mma_bf16(Yacc[nt], aH + 4, bH[2], bH[3]);
                mma_bf16(Yacc[nt], aH + 4, bL[2], bL[3]);
                mma_bf16(Yacc[nt], aL + 4, bH[2], bH[3]);
            }
        }
        __syncthreads();

        if (mc < 7) {
            load_phi(mc + 1); CPA_COMMIT();
            load_g(mc + 1);   CPA_COMMIT();
            CPA_WAIT1();
            __syncthreads();
        }
    }

    rs0 += __shfl_xor_sync(0xffffffffu, rs0, 1);
    rs0 += __shfl_xor_sync(0xffffffffu, rs0, 2);
    rs1 += __shfl_xor_sync(0xffffffffu, rs1, 1);
    rs1 += __shfl_xor_sync(0xffffffffu, rs1, 2);
    float* invs = (float*)(smem + O_INV);
    if (qc == 0) {
        invs[wrow + qr]     = 1.0f / rs0;
        invs[wrow + qr + 8] = 1.0f / rs1;
    }
    __syncthreads();

    // ---- epilogue: normalize, split to bf16, store y^T [b][n][ci] ---------
    int ci0 = wrow + qr;
#pragma unroll
    for (int nt = 0; nt < 16; nt++) {
        int nl2 = nt * 8 + qc * 2;
        float in0 = invs[nl2], in1 = invs[nl2 + 1];
        float y00 = Yacc[nt][0] * in0;   // (n,   ci0)
        float y01 = Yacc[nt][1] * in1;   // (n+1, ci0)
        float y10 = Yacc[nt][2] * in0;   // (n,   ci0+8)
        float y11 = Yacc[nt][3] * in1;   // (n+1, ci0+8)
        u64 r0 = ((u64)b * NN + n0 + nl2) * CI + ci0;
        u64 r1 = r0 + CI;
        __nv_bfloat16 h;
        h = __float2bfloat16_rn(y00);
        g_yTH[r0] = __bfloat16_as_ushort(h);
        g_yTL[r0] = __bfloat16_as_ushort(__float2bfloat16_rn(y00 - __bfloat162float(h)));
        h = __float2bfloat16_rn(y10);
        g_yTH[r0 + 8] = __bfloat16_as_ushort(h);
        g_yTL[r0 + 8] = __bfloat16_as_ushort(__float2bfloat16_rn(y10 - __bfloat162float(h)));
        h = __float2bfloat16_rn(y01);
        g_yTH[r1] = __bfloat16_as_ushort(h);
        g_yTL[r1] = __bfloat16_as_ushort(__float2bfloat16_rn(y01 - __bfloat162float(h)));
        h = __float2bfloat16_rn(y11);
        g_yTH[r1 + 8] = __bfloat16_as_ushort(h);
        g_yTL[r1 + 8] = __bfloat16_as_ushort(__float2bfloat16_rn(y11 - __bfloat162float(h)));
    }
}

// ---------------------------------------------------------------------------
// wproj_mma: z = Ww @ y + Wb, bf16x3 mma, K=128, + deterministic BN partials.
// ---------------------------------------------------------------------------
__global__ __launch_bounds__(256, 1) void wproj_mma_kernel(
    const float* __restrict__ bias)
{
    extern __shared__ char smem[];
    uint32_t sb = smem_u32(smem);
    const uint32_t O_AH = 0, O_AL = TILE_B, O_BH = 2 * TILE_B, O_BL = 3 * TILE_B;
    int b = blockIdx.z, o0 = blockIdx.y * 128, n0 = blockIdx.x * 128;
    int tid = threadIdx.x, lane = tid & 31, wid = tid >> 5;
    int wrow = wid * 16, qr = lane >> 2, qc = lane & 3;

#pragma unroll
    for (int j = 0; j < 8; j++) {
        int id = tid + j * 256;
        int row = id >> 4, seg = id & 15;
        uint32_t d = row * PADB + seg * 16;
        int wsrc = 98304 + (o0 + row) * 128 + seg * 8;
        u64 ysrc = ((u64)b * NN + n0 + row) * CI + seg * 8;
        cpa16(sb + O_AH + d, &g_wsH[wsrc]);
        cpa16(sb + O_AL + d, &g_wsL[wsrc]);
        cpa16(sb + O_BH + d, &g_yTH[ysrc]);
        cpa16(sb + O_BL + d, &g_yTL[ysrc]);
    }
    CPA_COMMIT(); CPA_WAIT0();
    __syncthreads();

    uint32_t a_row = (uint32_t)(wrow + (lane & 15));
    uint32_t a_seg = (uint32_t)((lane >> 4) << 4);
    uint32_t b_rlane = (uint32_t)(lane & 7);
    uint32_t b_seg = (uint32_t)((lane >> 3) << 4);

    float Dacc[16][4];
#pragma unroll
    for (int t = 0; t < 16; t++) { Dacc[t][0] = Dacc[t][1] = Dacc[t][2] = Dacc[t][3] = 0.f; }

#pragma unroll
    for (int kt = 0; kt < 8; kt += 2) {
        uint32_t aH[8], aL[8];
        uint32_t abase = a_row * PADB + kt * 32 + a_seg;
        ldm4(aH + 0, sb + O_AH + abase);
        ldm4(aH + 4, sb + O_AH + abase + 32);
        ldm4(aL + 0, sb + O_AL + abase);
        ldm4(aL + 4, sb + O_AL + abase + 32);
#pragma unroll
        for (int mt = 0; mt < 16; mt++) {
            uint32_t bH[4], bL[4];
            uint32_t bbase = (mt * 8 + b_rlane) * PADB + kt * 32 + b_seg;
            ldm4(bH, sb + O_BH + bbase);
            ldm4(bL, sb + O_BL + bbase);
            mma_bf16(Dacc[mt], aH + 0, bH[0], bH[1]);
            mma_bf16(Dacc[mt], aH + 0, bL[0], bL[1]);
            mma_bf16(Dacc[mt], aL + 0, bH[0], bH[1]);
            mma_bf16(Dacc[mt], aH + 4, bH[2], bH[3]);
            mma_bf16(Dacc[mt], aH + 4, bL[2], bL[3]);
            mma_bf16(Dacc[mt], aL + 4, bH[2], bH[3]);
        }
    }

    int og0 = o0 + wrow + qr, og1 = og0 + 8;
    float bv0 = bias[og0], bv1 = bias[og1];
    float* ob = g_z + (u64)b * CC * NN;
    float s0 = 0.f, q0 = 0.f, s1 = 0.f, q1 = 0.f;
#pragma unroll
    for (int mt = 0; mt < 16; mt++) {
        int n = n0 + mt * 8 + qc * 2;
        float v0 = Dacc[mt][0] + bv0, v1 = Dacc[mt][1] + bv0;
        float v2 = Dacc[mt][2] + bv1, v3 = Dacc[mt][3] + bv1;
        *(float2*)&ob[(u64)og0 * NN + n] = make_float2(v0, v1);
        *(float2*)&ob[(u64)og1 * NN + n] = make_float2(v2, v3);
        s0 += v0 + v1; q0 += v0 * v0 + v1 * v1;
        s1 += v2 + v3; q1 += v2 * v2 + v3 * v3;
    }
    s0 += __shfl_xor_sync(0xffffffffu, s0, 1);
    s0 += __shfl_xor_sync(0xffffffffu, s0, 2);
    q0 += __shfl_xor_sync(0xffffffffu, q0, 1);
    q0 += __shfl_xor_sync(0xffffffffu, q0, 2);
    s1 += __shfl_xor_sync(0xffffffffu, s1, 1);
    s1 += __shfl_xor_sync(0xffffffffu, s1, 2);
    q1 += __shfl_xor_sync(0xffffffffu, q1, 1);
    q1 += __shfl_xor_sync(0xffffffffu, q1, 2);
    if (qc == 0) {
        int slot = b * 32 + blockIdx.x;   // [0,256)
        g_psum  [og0 * 256 + slot] = s0;
        g_psumsq[og0 * 256 + slot] = q0;
        g_psum  [og1 * 256 + slot] = s1;
        g_psumsq[og1 * 256 + slot] = q1;
    }
}

// ---------------------------------------------------------------------------
__global__ void bnfin_kernel(const float* __restrict__ gamma,
                             const float* __restrict__ beta)
{
    int c = threadIdx.x;
    float s = 0.f, s2 = 0.f;
    for (int j = 0; j < 256; j++) { s += g_psum[c * 256 + j]; s2 += g_psumsq[c * 256 + j]; }
    const float inv_n = 1.0f / 32768.0f;
    float mean = s * inv_n;
    float var  = s2 * inv_n - mean * mean;
    float inv  = rsqrtf(var + 1e-5f);
    float a = gamma[c] * inv;
    g_bna[c] = a;
    g_bnb[c] = beta[c] - mean * a;
}

// ---------------------------------------------------------------------------
__global__ __launch_bounds__(256) void final_kernel(
    const float* __restrict__ x, float* __restrict__ out)
{
    int idx = blockIdx.x * 256 + threadIdx.x;
    u64 e = (u64)idx << 2;
    int c = (int)((e >> 12) & 255);
    float4 xv = *(const float4*)(x + e);
    float4 zv = *((const float4*)g_z + idx);
    float a = g_bna[c], bb = g_bnb[c];
    float4 o;
    o.x = fmaf(zv.x, a, bb) + xv.x;
    o.y = fmaf(zv.y, a, bb) + xv.y;
    o.z = fmaf(zv.z, a, bb) + xv.z;
    o.w = fmaf(zv.w, a, bb) + xv.w;
    *(float4*)(out + e) = o;
}

// ---------------------------------------------------------------------------
extern "C" void kernel_launch(void* const* d_in, const int* in_sizes, int n_in,
                              void* d_out, int out_size)
{
    const float* x     = (const float*)d_in[0];
    const float* tw    = (const float*)d_in[1];
    const float* tb    = (const float*)d_in[2];
    const float* pw    = (const float*)d_in[3];
    const float* pb    = (const float*)d_in[4];
    const float* gw    = (const float*)d_in[5];
    const float* gbv   = (const float*)d_in[6];
    const float* Ww    = (const float*)d_in[7];
    const float* Wb    = (const float*)d_in[8];
    const float* gamma = (const float*)d_in[9];
    const float* beta  = (const float*)d_in[10];
    float* out = (float*)d_out;

    cudaFuncSetAttribute(attn_mma_kernel,
                         cudaFuncAttributeMaxDynamicSharedMemorySize, ATT_SMEM);
    cudaFuncSetAttribute(proj_mma_kernel,
                         cudaFuncAttributeMaxDynamicSharedMemorySize, PRJ_SMEM);
    cudaFuncSetAttribute(wproj_mma_kernel,
                         cudaFuncAttributeMaxDynamicSharedMemorySize, PRJ_SMEM);

    xsplit_kernel<<<dim3(128, 8, 8), 256>>>(x);
    wsplit_kernel<<<512, 256>>>(tw, pw, gw, Ww);
    proj_mma_kernel<<<dim3(32, 3, 8), 256, PRJ_SMEM>>>(tb, pb, gbv);
    attn_mma_kernel<<<dim3(32, 8), 256, ATT_SMEM>>>();
    wproj_mma_kernel<<<dim3(32, 2, 8), 256, PRJ_SMEM>>>(Wb);
    bnfin_kernel<<<1, 256>>>(gamma, beta);
    final_kernel<<<8192, 256>>>(x, out);
}

// round 12
// speedup vs baseline: 2.7194x; 1.0696x over previous
#include <cuda_runtime.h>
#include <cuda_bf16.h>
#include <cstdint>

// ---------------------------------------------------------------------------
// NonLocalBlock: B=8, C=256, Ci=128, H=W=64, N=4096, M=1024
// ALL GEMMs on mma.sync bf16x3. proj/wproj: K-chunk 64, 2 CTAs/SM.
// theta pre-split in proj epilogue; pool fused; y-split fused; MUFU exp.
// ---------------------------------------------------------------------------

#define NB 8
#define CC 256
#define CI 128
#define NN 4096
#define MM 1024

typedef unsigned long long u64;

// exp(s - 20) via MUFU: 2^(s*log2e - 20*log2e)
__device__ __forceinline__ float exp_s(float s) {
    float r;
    float t = fmaf(s, 1.4426950408889634f, -28.853900817779268f);
    asm("ex2.approx.f32 %0, %1;" : "=f"(r) : "f"(t));
    return r;
}

// ----------------------- tensor-core helpers --------------------------------
__device__ __forceinline__ uint32_t smem_u32(const void* p) {
    uint32_t a;
    asm("{ .reg .u64 t; cvta.to.shared.u64 t, %1; cvt.u32.u64 %0, t; }" : "=r"(a) : "l"(p));
    return a;
}
__device__ __forceinline__ void ldm4(uint32_t* r, uint32_t addr) {
    asm volatile("ldmatrix.sync.aligned.m8n8.x4.shared.b16 {%0,%1,%2,%3}, [%4];"
        : "=r"(r[0]), "=r"(r[1]), "=r"(r[2]), "=r"(r[3]) : "r"(addr));
}
__device__ __forceinline__ void mma_bf16(float* c, const uint32_t* a,
                                         uint32_t b0, uint32_t b1) {
    asm volatile(
        "mma.sync.aligned.m16n8k16.row.col.f32.bf16.bf16.f32 "
        "{%0,%1,%2,%3}, {%4,%5,%6,%7}, {%8,%9}, {%0,%1,%2,%3};"
        : "+f"(c[0]), "+f"(c[1]), "+f"(c[2]), "+f"(c[3])
        : "r"(a[0]), "r"(a[1]), "r"(a[2]), "r"(a[3]), "r"(b0), "r"(b1));
}
__device__ __forceinline__ void cpa16(uint32_t dst, const void* src) {
    asm volatile("cp.async.cg.shared.global [%0], [%1], 16;" :: "r"(dst), "l"(src));
}
#define CPA_COMMIT() asm volatile("cp.async.commit_group;" ::: "memory")
#define CPA_WAIT0()  asm volatile("cp.async.wait_group 0;" ::: "memory")
#define CPA_WAIT1()  asm volatile("cp.async.wait_group 1;" ::: "memory")

__device__ __forceinline__ uint32_t pack_bf16x2(float a, float b) {
    __nv_bfloat16 ha = __float2bfloat16_rn(a), hb = __float2bfloat16_rn(b);
    return ((uint32_t)__bfloat16_as_ushort(hb) << 16) | (uint32_t)__bfloat16_as_ushort(ha);
}

// ----------------------------- scratch ------------------------------------
__device__ uint16_t g_thTH[NB * NN * CI];   // theta split [b][n][ci]
__device__ uint16_t g_thTL[NB * NN * CI];
__device__ uint16_t g_phiH[NB * MM * CI];   // pooled phi split [b][m][ci]
__device__ uint16_t g_phiL[NB * MM * CI];
__device__ uint16_t g_gHa [NB * CI * MM];   // pooled g split [b][ci][m]
__device__ uint16_t g_gLa [NB * CI * MM];
__device__ uint16_t g_xTH [NB * NN * CC];   // x^T split [b][n][c]
__device__ uint16_t g_xTL [NB * NN * CC];
__device__ uint16_t g_yTH [NB * NN * CI];   // y^T split [b][n][ci]
__device__ uint16_t g_yTL [NB * NN * CI];
__device__ uint16_t g_wsH [131072];         // tw|pw|gw (3x32768) then Ww (32768)
__device__ uint16_t g_wsL [131072];
__device__ float g_z    [NB * CC * NN];
__device__ float g_psum [CC * 256];
__device__ float g_psumsq[CC * 256];
__device__ float g_bna[CC], g_bnb[CC];

// ---------------------------------------------------------------------------
// xsplit: transpose + bf16 hi/lo split. x [b][256][4096] -> g_xTH/L [b][n][256].
// ---------------------------------------------------------------------------
__global__ __launch_bounds__(256) void xsplit_kernel(const float* __restrict__ src)
{
    __shared__ float t[32][33];
    int b = blockIdx.z, c0 = blockIdx.y * 32, n0 = blockIdx.x * 32;
    int tid = threadIdx.x;
    int cl = tid >> 3, ng = (tid & 7) * 4;
    float4 v = *(const float4*)&src[((u64)b * CC + c0 + cl) * NN + n0 + ng];
    t[cl][ng] = v.x; t[cl][ng + 1] = v.y; t[cl][ng + 2] = v.z; t[cl][ng + 3] = v.w;
    __syncthreads();
    int nl = tid >> 3, cg = (tid & 7) * 4;
    uint16_t hs[4], ls[4];
#pragma unroll
    for (int e = 0; e < 4; e++) {
        float val = t[cg + e][nl];
        __nv_bfloat16 h = __float2bfloat16_rn(val);
        __nv_bfloat16 l = __float2bfloat16_rn(val - __bfloat162float(h));
        hs[e] = __bfloat16_as_ushort(h); ls[e] = __bfloat16_as_ushort(l);
    }
    u64 di = ((u64)b * NN + n0 + nl) * CC + c0 + cg;
    *(uint2*)&g_xTH[di] = *(uint2*)hs;
    *(uint2*)&g_xTL[di] = *(uint2*)ls;
}

// ---------------------------------------------------------------------------
// wsplit: flat split of all weights into g_wsH/g_wsL.
// ---------------------------------------------------------------------------
__global__ __launch_bounds__(256) void wsplit_kernel(
    const float* __restrict__ tw, const float* __restrict__ pw,
    const float* __restrict__ gw, const float* __restrict__ Ww)
{
    int idx = blockIdx.x * 256 + threadIdx.x;   // 131072
    const float* src; int off;
    if (idx < 32768)       { src = tw; off = idx; }
    else if (idx < 65536)  { src = pw; off = idx - 32768; }
    else if (idx < 98304)  { src = gw; off = idx - 65536; }
    else                   { src = Ww; off = idx - 98304; }
    float v = src[off];
    __nv_bfloat16 h = __float2bfloat16_rn(v);
    __nv_bfloat16 l = __float2bfloat16_rn(v - __bfloat162float(h));
    g_wsH[idx] = __bfloat16_as_ushort(h);
    g_wsL[idx] = __bfloat16_as_ushort(l);
}

// ---------------------------------------------------------------------------
// proj_mma: out[o,n] = sum_c w[o,c] x[c,n] + bias[o], bf16x3 mma.
// K=256 in 4 chunks of 64; smem 72KB -> 2 CTAs/SM.
// pj=0 (theta): split-bf16 [n][ci] store. pj=1,2: fused pool + split store.
// ---------------------------------------------------------------------------
#define PADB2 144
#define TILE2 18432
#define PRJ_SMEM (4 * TILE2)

__global__ __launch_bounds__(256, 2) void proj_mma_kernel(
    const float* __restrict__ tb, const float* __restrict__ pb,
    const float* __restrict__ gb)
{
    extern __shared__ char smem[];
    uint32_t sb = smem_u32(smem);
    const uint32_t O_AH = 0, O_AL = TILE2, O_BH = 2 * TILE2, O_BL = 3 * TILE2;
    int b = blockIdx.z, pj = blockIdx.y, n0 = blockIdx.x * 128;
    int tid = threadIdx.x, lane = tid & 31, wid = tid >> 5;
    int wrow = wid * 16, qr = lane >> 2, qc = lane & 3;

    const uint16_t* wH = g_wsH + pj * 32768;
    const uint16_t* wL = g_wsL + pj * 32768;
    const float* bias = (pj == 0) ? tb : (pj == 1) ? pb : gb;

    uint32_t a_row = (uint32_t)(wrow + (lane & 15));
    uint32_t a_seg = (uint32_t)((lane >> 4) << 4);
    uint32_t b_rlane = (uint32_t)(lane & 7);
    uint32_t b_seg = (uint32_t)((lane >> 3) << 4);

    float Dacc[16][4];
#pragma unroll
    for (int t = 0; t < 16; t++) { Dacc[t][0] = Dacc[t][1] = Dacc[t][2] = Dacc[t][3] = 0.f; }

    for (int kc = 0; kc < 4; kc++) {
#pragma unroll
        for (int j = 0; j < 4; j++) {
            int id = tid + j * 256;
            int row = id >> 3, seg = id & 7;
            uint32_t d = row * PADB2 + seg * 16;
            int wsrc = row * 256 + kc * 64 + seg * 8;
            u64 xsrc = ((u64)b * NN + n0 + row) * CC + kc * 64 + seg * 8;
            cpa16(sb + O_AH + d, &wH[wsrc]);
            cpa16(sb + O_AL + d, &wL[wsrc]);
            cpa16(sb + O_BH + d, &g_xTH[xsrc]);
            cpa16(sb + O_BL + d, &g_xTL[xsrc]);
        }
        CPA_COMMIT(); CPA_WAIT0();
        __syncthreads();

#pragma unroll
        for (int kt = 0; kt < 4; kt += 2) {
            uint32_t aH[8], aL[8];
            uint32_t abase = a_row * PADB2 + kt * 32 + a_seg;
            ldm4(aH + 0, sb + O_AH + abase);
            ldm4(aH + 4, sb + O_AH + abase + 32);
            ldm4(aL + 0, sb + O_AL + abase);
            ldm4(aL + 4, sb + O_AL + abase + 32);
#pragma unroll
            for (int mt = 0; mt < 16; mt++) {
                uint32_t bH[4], bL[4];
                uint32_t bbase = (mt * 8 + b_rlane) * PADB2 + kt * 32 + b_seg;
                ldm4(bH, sb + O_BH + bbase);
                ldm4(bL, sb + O_BL + bbase);
                mma_bf16(Dacc[mt], aH + 0, bH[0], bH[1]);
                mma_bf16(Dacc[mt], aH + 0, bL[0], bL[1]);
                mma_bf16(Dacc[mt], aL + 0, bH[0], bH[1]);
                mma_bf16(Dacc[mt], aH + 4, bH[2], bH[3]);
                mma_bf16(Dacc[mt], aH + 4, bL[2], bL[3]);
                mma_bf16(Dacc[mt], aL + 4, bH[2], bH[3]);
            }
        }
        __syncthreads();
    }

    int o0 = wrow + qr;
    float bv0 = bias[o0], bv1 = bias[o0 + 8];

    if (pj == 0) {
        // theta: split-bf16 store [b][n][ci]
#pragma unroll
        for (int mt = 0; mt < 16; mt++) {
            int n = n0 + mt * 8 + qc * 2;
            float v0 = Dacc[mt][0] + bv0;   // (n,   o0)
            float v1 = Dacc[mt][1] + bv0;   // (n+1, o0)
            float v2 = Dacc[mt][2] + bv1;   // (n,   o0+8)
            float v3 = Dacc[mt][3] + bv1;   // (n+1, o0+8)
            u64 r0 = ((u64)b * NN + n) * CI + o0;
            u64 r1 = r0 + CI;
            __nv_bfloat16 h;
            h = __float2bfloat16_rn(v0);
            g_thTH[r0] = __bfloat16_as_ushort(h);
            g_thTL[r0] = __bfloat16_as_ushort(__float2bfloat16_rn(v0 - __bfloat162float(h)));
            h = __float2bfloat16_rn(v2);
            g_thTH[r0 + 8] = __bfloat16_as_ushort(h);
            g_thTL[r0 + 8] = __bfloat16_as_ushort(__float2bfloat16_rn(v2 - __bfloat162float(h)));
            h = __float2bfloat16_rn(v1);
            g_thTH[r1] = __bfloat16_as_ushort(h);
            g_thTL[r1] = __bfloat16_as_ushort(__float2bfloat16_rn(v1 - __bfloat162float(h)));
            h = __float2bfloat16_rn(v3);
            g_thTH[r1 + 8] = __bfloat16_as_ushort(h);
            g_thTL[r1 + 8] = __bfloat16_as_ushort(__float2bfloat16_rn(v3 - __bfloat162float(h)));
        }
    } else {
        uint16_t* dH = (pj == 1) ? g_phiH : g_gHa;
        uint16_t* dL = (pj == 1) ? g_phiL : g_gLa;
#pragma unroll
        for (int mt2 = 0; mt2 < 8; mt2++) {
            int m = blockIdx.x * 32 + mt2 * 4 + qc;
            float p0 = fmaxf(fmaxf(Dacc[mt2][0], Dacc[mt2][1]),
                             fmaxf(Dacc[mt2 + 8][0], Dacc[mt2 + 8][1])) + bv0;
            float p1 = fmaxf(fmaxf(Dacc[mt2][2], Dacc[mt2][3]),
                             fmaxf(Dacc[mt2 + 8][2], Dacc[mt2 + 8][3])) + bv1;
            __nv_bfloat16 h0 = __float2bfloat16_rn(p0);
            __nv_bfloat16 l0 = __float2bfloat16_rn(p0 - __bfloat162float(h0));
            __nv_bfloat16 h1 = __float2bfloat16_rn(p1);
            __nv_bfloat16 l1 = __float2bfloat16_rn(p1 - __bfloat162float(h1));
            u64 i0, i1;
            if (pj == 1) { i0 = ((u64)b * MM + m) * CI + o0; i1 = i0 + 8; }
            else         { i0 = ((u64)b * CI + o0) * MM + m; i1 = i0 + (u64)8 * MM; }
            dH[i0] = __bfloat16_as_ushort(h0); dL[i0] = __bfloat16_as_ushort(l0);
            dH[i1] = __bfloat16_as_ushort(h1); dL[i1] = __bfloat16_as_ushort(l1);
        }
    }
}

// ---------------------------------------------------------------------------
// K2: tensor-core attention. Theta loaded pre-split via cp.async.
// ---------------------------------------------------------------------------
#define PADB 272
#define TILE_B 34816
#define O_TH 0
#define O_TL 34816
#define O_PH 69632
#define O_PL 104448
#define O_GH 139264
#define O_GL 174080
#define O_INV 208896
#define ATT_SMEM 209920

__global__ __launch_bounds__(256, 1) void attn_mma_kernel()
{
    extern __shared__ char smem[];
    uint32_t sb = smem_u32(smem);
    int b = blockIdx.y, n0 = blockIdx.x * 128;
    int tid = threadIdx.x;
    int lane = tid & 31, wid = tid >> 5;
    int wrow = wid * 16;
    int qr = lane >> 2, qc = lane & 3;

    auto load_phi = [&](int mc) {
#pragma unroll
        for (int j = 0; j < 8; j++) {
            int id = tid + j * 256;
            int row = id >> 4, seg = id & 15;
            int src = (b * MM + mc * 128 + row) * CI + seg * 8;
            uint32_t d = row * PADB + seg * 16;
            cpa16(sb + O_PH + d, &g_phiH[src]);
            cpa16(sb + O_PL + d, &g_phiL[src]);
        }
    };
    auto load_g = [&](int mc) {
#pragma unroll
        for (int j = 0; j < 8; j++) {
            int id = tid + j * 256;
            int row = id >> 4, seg = id & 15;
            int src = (b * CI + row) * MM + mc * 128 + seg * 8;
            uint32_t d = row * PADB + seg * 16;
            cpa16(sb + O_GH + d, &g_gHa[src]);
            cpa16(sb + O_GL + d, &g_gLa[src]);
        }
    };

    // theta tile [n][ci] split via cp.async
#pragma unroll
    for (int j = 0; j < 8; j++) {
        int id = tid + j * 256;
        int row = id >> 4, seg = id & 15;
        u64 src = ((u64)b * NN + n0 + row) * CI + seg * 8;
        uint32_t d = row * PADB + seg * 16;
        cpa16(sb + O_TH + d, &g_thTH[src]);
        cpa16(sb + O_TL + d, &g_thTL[src]);
    }
    load_phi(0); CPA_COMMIT();
    load_g(0);   CPA_COMMIT();
    CPA_WAIT0();
    __syncthreads();

    float Yacc[16][4];
#pragma unroll
    for (int t = 0; t < 16; t++) { Yacc[t][0] = Yacc[t][1] = Yacc[t][2] = Yacc[t][3] = 0.f; }
    float rs0 = 0.f, rs1 = 0.f;

    uint32_t a_row = (uint32_t)(wrow + (lane & 15));
    uint32_t a_seg = (uint32_t)((lane >> 4) << 4);
    uint32_t b_rlane = (uint32_t)(lane & 7);
    uint32_t b_seg = (uint32_t)((lane >> 3) << 4);

    for (int mc = 0; mc < 8; mc++) {
        float Sacc[16][4];
#pragma unroll
        for (int t = 0; t < 16; t++) { Sacc[t][0] = Sacc[t][1] = Sacc[t][2] = Sacc[t][3] = 0.f; }

#pragma unroll
        for (int kt = 0; kt < 8; kt += 2) {
            uint32_t aH[8], aL[8];
            uint32_t abase = a_row * PADB + kt * 32 + a_seg;
            ldm4(aH + 0, sb + O_TH + abase);
            ldm4(aH + 4, sb + O_TH + abase + 32);
            ldm4(aL + 0, sb + O_TL + abase);
            ldm4(aL + 4, sb + O_TL + abase + 32);
#pragma unroll
            for (int mt = 0; mt < 16; mt++) {
                uint32_t bH[4], bL[4];
                uint32_t bbase = (mt * 8 + b_rlane) * PADB + kt * 32 + b_seg;
                ldm4(bH, sb + O_PH + bbase);
                ldm4(bL, sb + O_PL + bbase);
                mma_bf16(Sacc[mt], aH + 0, bH[0], bH[1]);
                mma_bf16(Sacc[mt], aH + 0, bL[0], bL[1]);
                mma_bf16(Sacc[mt], aL + 0, bH[0], bH[1]);
                mma_bf16(Sacc[mt], aH + 4, bH[2], bH[3]);
                mma_bf16(Sacc[mt], aH + 4, bL[2], bL[3]);
                mma_bf16(Sacc[mt], aL + 4, bH[2], bH[3]);
            }
        }
        __syncthreads();

        {
            int r0 = wrow + qr, r1 = r0 + 8;
#pragma unroll
            for (int mt = 0; mt < 16; mt++) {
                float e0 = exp_s(Sacc[mt][0]);
                float e1 = exp_s(Sacc[mt][1]);
                float e2 = exp_s(Sacc[mt][2]);
                float e3 = exp_s(Sacc[mt][3]);
                rs0 += e0 + e1; rs1 += e2 + e3;
                float h0 = __bfloat162float(__float2bfloat16_rn(e0));
                float h1 = __bfloat162float(__float2bfloat16_rn(e1));
                float h2 = __bfloat162float(__float2bfloat16_rn(e2));
                float h3 = __bfloat162float(__float2bfloat16_rn(e3));
                uint32_t off0 = r0 * PADB + mt * 16 + qc * 4;
                uint32_t off1 = r1 * PADB + mt * 16 + qc * 4;
                *(uint32_t*)(smem + O_PH + off0) = pack_bf16x2(h0, h1);
                *(uint32_t*)(smem + O_PH + off1) = pack_bf16x2(h2, h3);
                *(uint32_t*)(smem + O_PL + off0) = pack_bf16x2(e0 - h0, e1 - h1);
                *(uint32_t*)(smem + O_PL + off1) = pack_bf16x2(e2 - h2, e3 - h3);
            }
        }
        CPA_WAIT0();
        __syncthreads();

#pragma unroll
        for (int kt = 0; kt < 8; kt += 2) {
            uint32_t aH[8], aL[8];
            uint32_t abase = a_row * PADB + kt * 32 + a_seg;
            ldm4(aH + 0, sb + O_GH + abase);
            ldm4(aH + 4, sb + O_GH + abase + 32);
            ldm4(aL + 0, sb + O_GL + abase);
            ldm4(aL + 4, sb + O_GL + abase + 32);
#pragma unroll
            for (int nt = 0; nt < 16; nt++) {
                uint32_t bH[4], bL[4];
                uint32_t bbase = (nt * 8 + b_rlane) * PADB + kt * 32 + b_seg;
                ldm4(bH, sb + O_PH + bbase);
                ldm4(bL, sb + O_PL + bbase);
                mma_bf16(Yacc[nt], aH + 0, bH[0], bH[1]);
                mma_bf16(Yacc[nt], aH + 0, bL[0], bL[1]);
                mma_bf16(Yacc[nt], aL + 0, bH[0], bH[1]);
                mma_bf16(Yacc[nt], aH + 4, bH[2], bH[3]);
                mma_bf16(Yacc[nt], aH + 4, bL[2], bL[3]);
                mma_bf16(Yacc[nt], aL + 4, bH[2], bH[3]);
            }
        }
        __syncthreads();

        if (mc < 7) {
            load_phi(mc + 1); CPA_COMMIT();
            load_g(mc + 1);   CPA_COMMIT();
            CPA_WAIT1();
            __syncthreads();
        }
    }

    rs0 += __shfl_xor_sync(0xffffffffu, rs0, 1);
    rs0 += __shfl_xor_sync(0xffffffffu, rs0, 2);
    rs1 += __shfl_xor_sync(0xffffffffu, rs1, 1);
    rs1 += __shfl_xor_sync(0xffffffffu, rs1, 2);
    float* invs = (float*)(smem + O_INV);
    if (qc == 0) {
        invs[wrow + qr]     = 1.0f / rs0;
        invs[wrow + qr + 8] = 1.0f / rs1;
    }
    __syncthreads();

    // ---- epilogue: normalize, split to bf16, store y^T [b][n][ci] ---------
    int ci0 = wrow + qr;
#pragma unroll
    for (int nt = 0; nt < 16; nt++) {
        int nl2 = nt * 8 + qc * 2;
        float in0 = invs[nl2], in1 = invs[nl2 + 1];
        float y00 = Yacc[nt][0] * in0;
        float y01 = Yacc[nt][1] * in1;
        float y10 = Yacc[nt][2] * in0;
        float y11 = Yacc[nt][3] * in1;
        u64 r0 = ((u64)b * NN + n0 + nl2) * CI + ci0;
        u64 r1 = r0 + CI;
        __nv_bfloat16 h;
        h = __float2bfloat16_rn(y00);
        g_yTH[r0] = __bfloat16_as_ushort(h);
        g_yTL[r0] = __bfloat16_as_ushort(__float2bfloat16_rn(y00 - __bfloat162float(h)));
        h = __float2bfloat16_rn(y10);
        g_yTH[r0 + 8] = __bfloat16_as_ushort(h);
        g_yTL[r0 + 8] = __bfloat16_as_ushort(__float2bfloat16_rn(y10 - __bfloat162float(h)));
        h = __float2bfloat16_rn(y01);
        g_yTH[r1] = __bfloat16_as_ushort(h);
        g_yTL[r1] = __bfloat16_as_ushort(__float2bfloat16_rn(y01 - __bfloat162float(h)));
        h = __float2bfloat16_rn(y11);
        g_yTH[r1 + 8] = __bfloat16_as_ushort(h);
        g_yTL[r1 + 8] = __bfloat16_as_ushort(__float2bfloat16_rn(y11 - __bfloat162float(h)));
    }
}

// ---------------------------------------------------------------------------
// wproj_mma: z = Ww @ y + Wb, bf16x3, K=128 in 2 chunks of 64; 2 CTAs/SM.
// ---------------------------------------------------------------------------
__global__ __launch_bounds__(256, 2) void wproj_mma_kernel(
    const float* __restrict__ bias)
{
    extern __shared__ char smem[];
    uint32_t sb = smem_u32(smem);
    const uint32_t O_AH = 0, O_AL = TILE2, O_BH = 2 * TILE2, O_BL = 3 * TILE2;
    int b = blockIdx.z, o0 = blockIdx.y * 128, n0 = blockIdx.x * 128;
    int tid = threadIdx.x, lane = tid & 31, wid = tid >> 5;
    int wrow = wid * 16, qr = lane >> 2, qc = lane & 3;

    uint32_t a_row = (uint32_t)(wrow + (lane & 15));
    uint32_t a_seg = (uint32_t)((lane >> 4) << 4);
    uint32_t b_rlane = (uint32_t)(lane & 7);
    uint32_t b_seg = (uint32_t)((lane >> 3) << 4);

    float Dacc[16][4];
#pragma unroll
    for (int t = 0; t < 16; t++) { Dacc[t][0] = Dacc[t][1] = Dacc[t][2] = Dacc[t][3] = 0.f; }

    for (int kc = 0; kc < 2; kc++) {
#pragma unroll
        for (int j = 0; j < 4; j++) {
            int id = tid + j * 256;
            int row = id >> 3, seg = id & 7;
            uint32_t d = row * PADB2 + seg * 16;
            int wsrc = 98304 + (o0 + row) * 128 + kc * 64 + seg * 8;
            u64 ysrc = ((u64)b * NN + n0 + row) * CI + kc * 64 + seg * 8;
            cpa16(sb + O_AH + d, &g_wsH[wsrc]);
            cpa16(sb + O_AL + d, &g_wsL[wsrc]);
            cpa16(sb + O_BH + d, &g_yTH[ysrc]);
            cpa16(sb + O_BL + d, &g_yTL[ysrc]);
        }
        CPA_COMMIT(); CPA_WAIT0();
        __syncthreads();

#pragma unroll
        for (int kt = 0; kt < 4; kt += 2) {
            uint32_t aH[8], aL[8];
            uint32_t abase = a_row * PADB2 + kt * 32 + a_seg;
            ldm4(aH + 0, sb + O_AH + abase);
            ldm4(aH + 4, sb + O_AH + abase + 32);
            ldm4(aL + 0, sb + O_AL + abase);
            ldm4(aL + 4, sb + O_AL + abase + 32);
#pragma unroll
            for (int mt = 0; mt < 16; mt++) {
                uint32_t bH[4], bL[4];
                uint32_t bbase = (mt * 8 + b_rlane) * PADB2 + kt * 32 + b_seg;
                ldm4(bH, sb + O_BH + bbase);
                ldm4(bL, sb + O_BL + bbase);
                mma_bf16(Dacc[mt], aH + 0, bH[0], bH[1]);
                mma_bf16(Dacc[mt], aH + 0, bL[0], bL[1]);
                mma_bf16(Dacc[mt], aL + 0, bH[0], bH[1]);
                mma_bf16(Dacc[mt], aH + 4, bH[2], bH[3]);
                mma_bf16(Dacc[mt], aH + 4, bL[2], bL[3]);
                mma_bf16(Dacc[mt], aL + 4, bH[2], bH[3]);
            }
        }
        __syncthreads();
    }

    int og0 = o0 + wrow + qr, og1 = og0 + 8;
    float bv0 = bias[og0], bv1 = bias[og1];
    float* ob = g_z + (u64)b * CC * NN;
    float s0 = 0.f, q0 = 0.f, s1 = 0.f, q1 = 0.f;
#pragma unroll
    for (int mt = 0; mt < 16; mt++) {
        int n = n0 + mt * 8 + qc * 2;
        float v0 = Dacc[mt][0] + bv0, v1 = Dacc[mt][1] + bv0;
        float v2 = Dacc[mt][2] + bv1, v3 = Dacc[mt][3] + bv1;
        *(float2*)&ob[(u64)og0 * NN + n] = make_float2(v0, v1);
        *(float2*)&ob[(u64)og1 * NN + n] = make_float2(v2, v3);
        s0 += v0 + v1; q0 += v0 * v0 + v1 * v1;
        s1 += v2 + v3; q1 += v2 * v2 + v3 * v3;
    }
    s0 += __shfl_xor_sync(0xffffffffu, s0, 1);
    s0 += __shfl_xor_sync(0xffffffffu, s0, 2);
    q0 += __shfl_xor_sync(0xffffffffu, q0, 1);
    q0 += __shfl_xor_sync(0xffffffffu, q0, 2);
    s1 += __shfl_xor_sync(0xffffffffu, s1, 1);
    s1 += __shfl_xor_sync(0xffffffffu, s1, 2);
    q1 += __shfl_xor_sync(0xffffffffu, q1, 1);
    q1 += __shfl_xor_sync(0xffffffffu, q1, 2);
    if (qc == 0) {
        int slot = b * 32 + blockIdx.x;   // [0,256)
        g_psum  [og0 * 256 + slot] = s0;
        g_psumsq[og0 * 256 + slot] = q0;
        g_psum  [og1 * 256 + slot] = s1;
        g_psumsq[og1 * 256 + slot] = q1;
    }
}

// ---------------------------------------------------------------------------
__global__ void bnfin_kernel(const float* __restrict__ gamma,
                             const float* __restrict__ beta)
{
    int c = threadIdx.x;
    float s = 0.f, s2 = 0.f;
    for (int j = 0; j < 256; j++) { s += g_psum[c * 256 + j]; s2 += g_psumsq[c * 256 + j]; }
    const float inv_n = 1.0f / 32768.0f;
    float mean = s * inv_n;
    float var  = s2 * inv_n - mean * mean;
    float inv  = rsqrtf(var + 1e-5f);
    float a = gamma[c] * inv;
    g_bna[c] = a;
    g_bnb[c] = beta[c] - mean * a;
}

// ---------------------------------------------------------------------------
__global__ __launch_bounds__(256) void final_kernel(
    const float* __restrict__ x, float* __restrict__ out)
{
    int idx = blockIdx.x * 256 + threadIdx.x;
    u64 e = (u64)idx << 2;
    int c = (int)((e >> 12) & 255);
    float4 xv = *(const float4*)(x + e);
    float4 zv = *((const float4*)g_z + idx);
    float a = g_bna[c], bb = g_bnb[c];
    float4 o;
    o.x = fmaf(zv.x, a, bb) + xv.x;
    o.y = fmaf(zv.y, a, bb) + xv.y;
    o.z = fmaf(zv.z, a, bb) + xv.z;
    o.w = fmaf(zv.w, a, bb) + xv.w;
    *(float4*)(out + e) = o;
}

// ---------------------------------------------------------------------------
extern "C" void kernel_launch(void* const* d_in, const int* in_sizes, int n_in,
                              void* d_out, int out_size)
{
    const float* x     = (const float*)d_in[0];
    const float* tw    = (const float*)d_in[1];
    const float* tb    = (const float*)d_in[2];
    const float* pw    = (const float*)d_in[3];
    const float* pb    = (const float*)d_in[4];
    const float* gw    = (const float*)d_in[5];
    const float* gbv   = (const float*)d_in[6];
    const float* Ww    = (const float*)d_in[7];
    const float* Wb    = (const float*)d_in[8];
    const float* gamma = (const float*)d_in[9];
    const float* beta  = (const float*)d_in[10];
    float* out = (float*)d_out;

    cudaFuncSetAttribute(attn_mma_kernel,
                         cudaFuncAttributeMaxDynamicSharedMemorySize, ATT_SMEM);
    cudaFuncSetAttribute(proj_mma_kernel,
                         cudaFuncAttributeMaxDynamicSharedMemorySize, PRJ_SMEM);
    cudaFuncSetAttribute(wproj_mma_kernel,
                         cudaFuncAttributeMaxDynamicSharedMemorySize, PRJ_SMEM);

    xsplit_kernel<<<dim3(128, 8, 8), 256>>>(x);
    wsplit_kernel<<<512, 256>>>(tw, pw, gw, Ww);
    proj_mma_kernel<<<dim3(32, 3, 8), 256, PRJ_SMEM>>>(tb, pb, gbv);
    attn_mma_kernel<<<dim3(32, 8), 256, ATT_SMEM>>>();
    wproj_mma_kernel<<<dim3(32, 2, 8), 256, PRJ_SMEM>>>(Wb);
    bnfin_kernel<<<1, 256>>>(gamma, beta);
    final_kernel<<<8192, 256>>>(x, out);
}